// round 14
// baseline (speedup 1.0000x reference)
#include <cuda_runtime.h>
#include <cuda_fp16.h>
#include <math.h>
#include <stdint.h>

// ---------------- problem constants ----------------
#define NTOK   2048
#define NEXP   64
#define TOPK   6
#define CAP    512
#define HDIM   2048
#define IDIM   768
#define TWOI   1536
#define SIDIM  1536

// ---------------- tile config ----------------
#define BK   32              // k per slab (halfs)
#define NTH  256             // 8 warps
#define RSA  80              // [row][k] tile row stride BYTES (32 halfs + 16 pad)
#define RSB  272             // [k][n] tile row stride BYTES (128 halfs + 8 pad)
#define TSLOT 10240          // bytes per tile slot
#define SWIGLU_SMEM (12 * TSLOT)  // 4-slot ring x (A,G,U) = 122880 B
#define GEMM_SMEM   (16 * TSLOT)  // 8-slot ring x (A,B)   = 163840 B

// router K-split
#define RKC 4
#define RKLEN (HDIM / RKC)   // 512

// ---------------- scratch ----------------
__device__ int   g_counts[NEXP];
__device__ int   g_buf_tok[NEXP * CAP];
__device__ float g_buf_w[NEXP * CAP];
__device__ float g_logits_p[RKC * NTOK * NEXP];
__device__ float g_hid[(size_t)NEXP * CAP * IDIM];
__device__ float g_shid[(size_t)NTOK * SIDIM];

// ---------------- helpers ----------------
__device__ __forceinline__ uint32_t smem_u32(const void* p) {
    uint32_t a;
    asm("{ .reg .u64 t; cvta.to.shared.u64 t, %1; cvt.u32.u64 %0, t; }" : "=r"(a) : "l"(p));
    return a;
}
__device__ __forceinline__ uint32_t pack2(float a, float b) {
    __half2 h = __floats2half2_rn(a, b);
    return *(uint32_t*)&h;
}
__device__ __forceinline__ void ldsm4(uint32_t r[4], uint32_t addr) {
    asm volatile("ldmatrix.sync.aligned.m8n8.x4.shared.b16 {%0,%1,%2,%3}, [%4];"
                 : "=r"(r[0]), "=r"(r[1]), "=r"(r[2]), "=r"(r[3]) : "r"(addr));
}
__device__ __forceinline__ void ldsm4t(uint32_t r[4], uint32_t addr) {
    asm volatile("ldmatrix.sync.aligned.m8n8.x4.trans.shared.b16 {%0,%1,%2,%3}, [%4];"
                 : "=r"(r[0]), "=r"(r[1]), "=r"(r[2]), "=r"(r[3]) : "r"(addr));
}
__device__ __forceinline__ void mma16(float c[4], const uint32_t a[4], const uint32_t b[2]) {
    asm volatile(
        "mma.sync.aligned.m16n8k16.row.col.f32.f16.f16.f32 "
        "{%0,%1,%2,%3}, {%4,%5,%6,%7}, {%8,%9}, {%0,%1,%2,%3};"
        : "+f"(c[0]), "+f"(c[1]), "+f"(c[2]), "+f"(c[3])
        : "r"(a[0]), "r"(a[1]), "r"(a[2]), "r"(a[3]), "r"(b[0]), "r"(b[1]));
}
__device__ __forceinline__ unsigned f2tf(float x) {
    unsigned y;
    asm("cvt.rna.tf32.f32 %0, %1;" : "=r"(y) : "f"(x));
    return y;
}
__device__ __forceinline__ void mma8(float c[4], const unsigned a[4], const unsigned b[2]) {
    asm volatile(
        "mma.sync.aligned.m16n8k8.row.col.f32.tf32.tf32.f32 "
        "{%0,%1,%2,%3}, {%4,%5,%6,%7}, {%8,%9}, {%0,%1,%2,%3};"
        : "+f"(c[0]), "+f"(c[1]), "+f"(c[2]), "+f"(c[3])
        : "r"(a[0]), "r"(a[1]), "r"(a[2]), "r"(a[3]), "r"(b[0]), "r"(b[1]));
}
__device__ __forceinline__ float silu_f(float v) { return v / (1.0f + expf(-v)); }

// ldmatrix per-lane byte offsets:
#define LM_A(lane)  (((((lane) >> 3) & 1) * 8 + ((lane) & 7)) * RSA + ((lane) >> 4) * 16)
#define LM_BN(lane) ((((lane) >> 4) * 8 + ((lane) & 7)) * RSA + (((lane) >> 3) & 1) * 16)
#define LM_BT(lane) (((((lane) >> 3) & 1) * 8 + ((lane) & 7)) * RSB + ((lane) >> 4) * 16)

// ================= fused SwiGLU up-projection (fp16, BK=32, 4-slot ring) =================
// MB = M block rows (128 or 64). 8 warps: 2(M) x 4(N); warp tile (MB/2) x 32, dual acc.
template<int MB, int BNK, int EXPERT, int GATHER>
__global__ __launch_bounds__(NTH) void k_swiglu(
    const float* __restrict__ Abase, const float* __restrict__ Bg0,
    const float* __restrict__ Bu0, float* __restrict__ C,
    int Kd, int ldb, int ldc, long sB, long sC)
{
    constexpr int MTI = MB / 32;     // 16-row tiles per warp
    constexpr int ACH = MB / 32;     // A loader chunks per thread
    extern __shared__ __align__(16) unsigned char smraw[];
    __shared__ int s_tok[128];

    const int tid = threadIdx.x;
    const int warp = tid >> 5, lane = tid & 31;
    const int wm = warp >> 2, wn = warp & 3;
    const int gq = lane >> 2, tq = lane & 3;
    const int m0 = blockIdx.y * MB, n0 = blockIdx.x * 128;

    int e = 0, cnt = 0x40000000;
    if (EXPERT) {
        e = blockIdx.z;
        cnt = g_counts[e];
        if (m0 >= cnt) return;
    }
    if (GATHER) {
        if (tid < MB) {
            int p = m0 + tid;
            s_tok[tid] = (p < cnt) ? g_buf_tok[e * CAP + p] : 0;
        }
        __syncthreads();
    }

    const uint32_t smb = smem_u32(smraw);

    // ---- loaders ----
    const float* pa[4];
    uint32_t stA[4];
#pragma unroll
    for (int j = 0; j < ACH; j++) {
        int idx = tid + j * NTH;
        int m = idx >> 3, k8 = idx & 7;
        if (GATHER) pa[j] = Abase + (size_t)s_tok[m] * Kd + k8 * 4;
        else        pa[j] = Abase + (size_t)(m0 + m) * Kd + k8 * 4;
        stA[j] = (uint32_t)(m * RSA + k8 * 8);
    }
    const float* pg[4]; const float* pu[4];
    uint32_t stB[4];
#pragma unroll
    for (int j = 0; j < 4; j++) {
        int idx = tid + j * NTH;
        if (BNK) {
            int n = idx >> 3, k8 = idx & 7;
            pg[j] = Bg0 + (EXPERT ? (size_t)e * sB : 0) + (size_t)(n0 + n) * Kd + k8 * 4;
            pu[j] = Bu0 + (EXPERT ? (size_t)e * sB : 0) + (size_t)(n0 + n) * Kd + k8 * 4;
            stB[j] = (uint32_t)(n * RSA + k8 * 8);
        } else {
            int k = idx >> 5, n8 = idx & 31;
            pg[j] = Bg0 + (EXPERT ? (size_t)e * sB : 0) + (size_t)k * ldb + n0 + n8 * 4;
            pu[j] = Bu0 + (EXPERT ? (size_t)e * sB : 0) + (size_t)k * ldb + n0 + n8 * 4;
            stB[j] = (uint32_t)(k * RSB + n8 * 8);
        }
    }
    const long bumpB = BNK ? (long)BK : (long)BK * ldb;

    float4 ra[4], rg[4], ru[4];
    auto LDG = [&]() {
#pragma unroll
        for (int j = 0; j < ACH; j++) { ra[j] = *(const float4*)pa[j]; pa[j] += BK; }
#pragma unroll
        for (int j = 0; j < 4; j++) { rg[j] = *(const float4*)pg[j]; pg[j] += bumpB; }
#pragma unroll
        for (int j = 0; j < 4; j++) { ru[j] = *(const float4*)pu[j]; pu[j] += bumpB; }
    };
    auto STS = [&](int slot) {
        uint32_t aT = smb + slot * TSLOT;
        uint32_t gT = smb + 4 * TSLOT + slot * TSLOT;
        uint32_t uT = smb + 8 * TSLOT + slot * TSLOT;
#pragma unroll
        for (int j = 0; j < ACH; j++) {
            uint2 v = make_uint2(pack2(ra[j].x, ra[j].y), pack2(ra[j].z, ra[j].w));
            asm volatile("st.shared.v2.u32 [%0], {%1, %2};" :: "r"(aT + stA[j]), "r"(v.x), "r"(v.y));
        }
#pragma unroll
        for (int j = 0; j < 4; j++) {
            uint2 vg = make_uint2(pack2(rg[j].x, rg[j].y), pack2(rg[j].z, rg[j].w));
            asm volatile("st.shared.v2.u32 [%0], {%1, %2};" :: "r"(gT + stB[j]), "r"(vg.x), "r"(vg.y));
            uint2 vu = make_uint2(pack2(ru[j].x, ru[j].y), pack2(ru[j].z, ru[j].w));
            asm volatile("st.shared.v2.u32 [%0], {%1, %2};" :: "r"(uT + stB[j]), "r"(vu.x), "r"(vu.y));
        }
    };

    uint32_t aOff[MTI];
#pragma unroll
    for (int mt = 0; mt < MTI; mt++)
        aOff[mt] = (uint32_t)((wm * (MB / 2) + mt * 16) * RSA) + LM_A(lane);
    uint32_t bOff[2];
#pragma unroll
    for (int p = 0; p < 2; p++)
        bOff[p] = BNK ? (uint32_t)((wn * 32 + p * 16) * RSA) + LM_BN(lane)
                      : (uint32_t)((wn * 32 + p * 16) * 2) + LM_BT(lane);

    float accg[MTI][4][4], accu[MTI][4][4];
#pragma unroll
    for (int mt = 0; mt < MTI; mt++)
#pragma unroll
        for (int nt = 0; nt < 4; nt++)
#pragma unroll
            for (int r = 0; r < 4; r++) { accg[mt][nt][r] = 0.0f; accu[mt][nt][r] = 0.0f; }

    auto COMPUTE = [&](int slot) {
        uint32_t aT = smb + slot * TSLOT;
        uint32_t gT = smb + 4 * TSLOT + slot * TSLOT;
        uint32_t uT = smb + 8 * TSLOT + slot * TSLOT;
#pragma unroll
        for (int kh = 0; kh < 2; kh++) {
            const uint32_t kA = kh * 32;
            const uint32_t kB = BNK ? (uint32_t)(kh * 32) : (uint32_t)(kh * 16 * RSB);
            uint32_t af[MTI][4];
#pragma unroll
            for (int mt = 0; mt < MTI; mt++) ldsm4(af[mt], aT + aOff[mt] + kA);
            uint32_t bg[4][2], bu[4][2];
#pragma unroll
            for (int p = 0; p < 2; p++) {
                uint32_t t[4];
                if (BNK) ldsm4(t, gT + bOff[p] + kB); else ldsm4t(t, gT + bOff[p] + kB);
                bg[2 * p][0] = t[0]; bg[2 * p][1] = t[1];
                bg[2 * p + 1][0] = t[2]; bg[2 * p + 1][1] = t[3];
                if (BNK) ldsm4(t, uT + bOff[p] + kB); else ldsm4t(t, uT + bOff[p] + kB);
                bu[2 * p][0] = t[0]; bu[2 * p][1] = t[1];
                bu[2 * p + 1][0] = t[2]; bu[2 * p + 1][1] = t[3];
            }
#pragma unroll
            for (int mt = 0; mt < MTI; mt++)
#pragma unroll
                for (int nt = 0; nt < 4; nt++) {
                    mma16(accg[mt][nt], af[mt], bg[nt]);
                    mma16(accu[mt][nt], af[mt], bu[nt]);
                }
        }
    };

    const int nslab = Kd / BK;
    LDG(); STS(0);
    LDG(); STS(1);

    for (int t = 0; t < nslab / 2; t++) {
        __syncthreads();
        const int s0 = 2 * t, s1 = 2 * t + 1;
        const bool pf0 = (s0 + 2 < nslab), pf1 = (s1 + 2 < nslab);
        if (pf0) LDG();
        COMPUTE(s0 & 3);
        if (pf0) STS((s0 + 2) & 3);
        if (pf1) LDG();
        COMPUTE(s1 & 3);
        if (pf1) STS((s1 + 2) & 3);
    }

    // ---- epilogue: silu(g)*u ----
#pragma unroll
    for (int mt = 0; mt < MTI; mt++)
#pragma unroll
        for (int nt = 0; nt < 4; nt++)
#pragma unroll
            for (int r = 0; r < 4; r++) {
                int row = wm * (MB / 2) + mt * 16 + gq + ((r & 2) ? 8 : 0);
                int col = wn * 32 + nt * 8 + tq * 2 + (r & 1);
                int gm = m0 + row;
                if (EXPERT && gm >= cnt) continue;
                float g = accg[mt][nt][r], u = accu[mt][nt][r];
                float* dst = C + (EXPERT ? (size_t)e * sC : 0);
                dst[(size_t)gm * ldc + n0 + col] = silu_f(g) * u;
            }
}

// ================= down GEMM (fp16, BK=32, 8-slot ring, sync per 4 slabs) =================
template<int MB, int BNK, int EXPERT, int ATOMIC>
__global__ __launch_bounds__(NTH) void k_gemm(
    const float* __restrict__ Abase, const float* __restrict__ Bbase,
    float* __restrict__ C, int Kd, int ldb, int ldc,
    long sA, long sB)
{
    constexpr int MTI = MB / 32;
    constexpr int ACH = MB / 32;
    extern __shared__ __align__(16) unsigned char smraw[];
    __shared__ int   s_tok[128];
    __shared__ float s_w[128];

    const int tid = threadIdx.x;
    const int warp = tid >> 5, lane = tid & 31;
    const int wm = warp >> 2, wn = warp & 3;
    const int gq = lane >> 2, tq = lane & 3;
    const int m0 = blockIdx.y * MB, n0 = blockIdx.x * 128;

    int e = 0, cnt = 0x40000000;
    if (EXPERT) {
        e = blockIdx.z;
        cnt = g_counts[e];
        if (m0 >= cnt) return;
    }
    if (ATOMIC) {
        if (tid < MB) {
            int p = m0 + tid;
            int ok = (p < cnt);
            s_tok[tid] = ok ? g_buf_tok[e * CAP + p] : 0;
            s_w[tid]   = ok ? g_buf_w[e * CAP + p] : 0.0f;
        }
        __syncthreads();
    }

    const uint32_t smb = smem_u32(smraw);

    const float* pa[4];
    uint32_t stA[4];
#pragma unroll
    for (int j = 0; j < ACH; j++) {
        int idx = tid + j * NTH;
        int m = idx >> 3, k8 = idx & 7;
        pa[j] = Abase + (EXPERT ? (size_t)e * sA : 0) + (size_t)(m0 + m) * Kd + k8 * 4;
        stA[j] = (uint32_t)(m * RSA + k8 * 8);
    }
    const float* pb[4];
    uint32_t stB[4];
#pragma unroll
    for (int j = 0; j < 4; j++) {
        int idx = tid + j * NTH;
        if (BNK) {
            int n = idx >> 3, k8 = idx & 7;
            pb[j] = Bbase + (EXPERT ? (size_t)e * sB : 0) + (size_t)(n0 + n) * Kd + k8 * 4;
            stB[j] = (uint32_t)(n * RSA + k8 * 8);
        } else {
            int k = idx >> 5, n8 = idx & 31;
            pb[j] = Bbase + (EXPERT ? (size_t)e * sB : 0) + (size_t)k * ldb + n0 + n8 * 4;
            stB[j] = (uint32_t)(k * RSB + n8 * 8);
        }
    }
    const long bumpB = BNK ? (long)BK : (long)BK * ldb;

    float4 ra[4], rb[4];
    auto LDG = [&]() {
#pragma unroll
        for (int j = 0; j < ACH; j++) { ra[j] = *(const float4*)pa[j]; pa[j] += BK; }
#pragma unroll
        for (int j = 0; j < 4; j++) { rb[j] = *(const float4*)pb[j]; pb[j] += bumpB; }
    };
    auto STS = [&](int slot) {
        uint32_t aT = smb + slot * TSLOT;
        uint32_t bT = smb + 8 * TSLOT + slot * TSLOT;
#pragma unroll
        for (int j = 0; j < ACH; j++) {
            uint2 v = make_uint2(pack2(ra[j].x, ra[j].y), pack2(ra[j].z, ra[j].w));
            asm volatile("st.shared.v2.u32 [%0], {%1, %2};" :: "r"(aT + stA[j]), "r"(v.x), "r"(v.y));
        }
#pragma unroll
        for (int j = 0; j < 4; j++) {
            uint2 v = make_uint2(pack2(rb[j].x, rb[j].y), pack2(rb[j].z, rb[j].w));
            asm volatile("st.shared.v2.u32 [%0], {%1, %2};" :: "r"(bT + stB[j]), "r"(v.x), "r"(v.y));
        }
    };

    uint32_t aOff[MTI];
#pragma unroll
    for (int mt = 0; mt < MTI; mt++)
        aOff[mt] = (uint32_t)((wm * (MB / 2) + mt * 16) * RSA) + LM_A(lane);
    uint32_t bOff[2];
#pragma unroll
    for (int p = 0; p < 2; p++)
        bOff[p] = BNK ? (uint32_t)((wn * 32 + p * 16) * RSA) + LM_BN(lane)
                      : (uint32_t)((wn * 32 + p * 16) * 2) + LM_BT(lane);

    float acc[MTI][4][4];
#pragma unroll
    for (int mt = 0; mt < MTI; mt++)
#pragma unroll
        for (int nt = 0; nt < 4; nt++)
#pragma unroll
            for (int r = 0; r < 4; r++) acc[mt][nt][r] = 0.0f;

    auto COMPUTE = [&](int slot) {
        uint32_t aT = smb + slot * TSLOT;
        uint32_t bT = smb + 8 * TSLOT + slot * TSLOT;
#pragma unroll
        for (int kh = 0; kh < 2; kh++) {
            const uint32_t kA = kh * 32;
            const uint32_t kB = BNK ? (uint32_t)(kh * 32) : (uint32_t)(kh * 16 * RSB);
            uint32_t af[MTI][4];
#pragma unroll
            for (int mt = 0; mt < MTI; mt++) ldsm4(af[mt], aT + aOff[mt] + kA);
            uint32_t bf[4][2];
#pragma unroll
            for (int p = 0; p < 2; p++) {
                uint32_t t[4];
                if (BNK) ldsm4(t, bT + bOff[p] + kB); else ldsm4t(t, bT + bOff[p] + kB);
                bf[2 * p][0] = t[0]; bf[2 * p][1] = t[1];
                bf[2 * p + 1][0] = t[2]; bf[2 * p + 1][1] = t[3];
            }
#pragma unroll
            for (int mt = 0; mt < MTI; mt++)
#pragma unroll
                for (int nt = 0; nt < 4; nt++)
                    mma16(acc[mt][nt], af[mt], bf[nt]);
        }
    };

    const int nslab = Kd / BK;          // 48 or 24: divisible by 4
    LDG(); STS(0);
    LDG(); STS(1);
    LDG(); STS(2);
    LDG(); STS(3);

    for (int t = 0; t < nslab / 4; t++) {
        __syncthreads();
#pragma unroll
        for (int i = 0; i < 4; i++) {
            const int s = 4 * t + i;
            const bool pf = (s + 4 < nslab);
            if (pf) LDG();
            COMPUTE(s & 7);
            if (pf) STS((s + 4) & 7);
        }
    }

#pragma unroll
    for (int mt = 0; mt < MTI; mt++)
#pragma unroll
        for (int nt = 0; nt < 4; nt++)
#pragma unroll
            for (int r = 0; r < 4; r++) {
                int row = wm * (MB / 2) + mt * 16 + gq + ((r & 2) ? 8 : 0);
                int col = wn * 32 + nt * 8 + tq * 2 + (r & 1);
                int gm = m0 + row;
                if (EXPERT && gm >= cnt) continue;
                if (ATOMIC) {
                    atomicAdd(&C[(size_t)s_tok[row] * ldc + n0 + col],
                              acc[mt][nt][r] * s_w[row]);
                } else {
                    C[(size_t)gm * ldc + n0 + col] = acc[mt][nt][r];
                }
            }
}

// ================= router logits: 3xTF32, K-split x4 (near-fp32, exact top-k) =================
#define RTH 128
__global__ __launch_bounds__(RTH) void k_router_gemm(const float* __restrict__ A,
                                                     const float* __restrict__ B) {
    __shared__ float As[16][64 + 4];
    __shared__ float Bsm[16][64 + 4];
    int tid = threadIdx.x;
    int warp = tid >> 5, lane = tid & 31;
    int wm = warp >> 1, wn = warp & 1, gq = lane >> 2, tq = lane & 3;
    int m0 = blockIdx.y * 64;
    int kc = blockIdx.x;
    int kbase = kc * RKLEN;

    const float* Ab = A + (size_t)m0 * HDIM + kbase;
    const float* Bb = B + kbase;

    float acc[2][4][4];
#pragma unroll
    for (int mt = 0; mt < 2; mt++)
#pragma unroll
        for (int nt = 0; nt < 4; nt++)
#pragma unroll
            for (int r = 0; r < 4; r++) acc[mt][nt][r] = 0.0f;

    for (int k0 = 0; k0 < RKLEN; k0 += 16) {
        __syncthreads();
#pragma unroll
        for (int j = 0; j < 2; j++) {
            int it = tid + j * RTH;
            int r = it >> 2, c4 = it & 3;
            float4 va = *(const float4*)(Ab + (size_t)r * HDIM + k0 + c4 * 4);
            As[c4 * 4 + 0][r] = va.x; As[c4 * 4 + 1][r] = va.y;
            As[c4 * 4 + 2][r] = va.z; As[c4 * 4 + 3][r] = va.w;
            float4 vb = *(const float4*)(Bb + (size_t)r * HDIM + k0 + c4 * 4);
            Bsm[c4 * 4 + 0][r] = vb.x; Bsm[c4 * 4 + 1][r] = vb.y;
            Bsm[c4 * 4 + 2][r] = vb.z; Bsm[c4 * 4 + 3][r] = vb.w;
        }
        __syncthreads();
#pragma unroll
        for (int kk = 0; kk < 16; kk += 8) {
            float af[2][4], bfv[4][2];
#pragma unroll
            for (int mt = 0; mt < 2; mt++) {
                int rb = wm * 32 + mt * 16;
                af[mt][0] = As[kk + tq    ][rb + gq    ];
                af[mt][1] = As[kk + tq    ][rb + gq + 8];
                af[mt][2] = As[kk + tq + 4][rb + gq    ];
                af[mt][3] = As[kk + tq + 4][rb + gq + 8];
            }
#pragma unroll
            for (int nt = 0; nt < 4; nt++) {
                int cb = wn * 32 + nt * 8 + gq;
                bfv[nt][0] = Bsm[kk + tq    ][cb];
                bfv[nt][1] = Bsm[kk + tq + 4][cb];
            }
            unsigned ah[2][4], al[2][4], bh[4][2], bl[4][2];
#pragma unroll
            for (int mt = 0; mt < 2; mt++)
#pragma unroll
                for (int i = 0; i < 4; i++) {
                    ah[mt][i] = f2tf(af[mt][i]);
                    al[mt][i] = f2tf(af[mt][i] - __uint_as_float(ah[mt][i]));
                }
#pragma unroll
            for (int nt = 0; nt < 4; nt++)
#pragma unroll
                for (int i = 0; i < 2; i++) {
                    bh[nt][i] = f2tf(bfv[nt][i]);
                    bl[nt][i] = f2tf(bfv[nt][i] - __uint_as_float(bh[nt][i]));
                }
#pragma unroll
            for (int mt = 0; mt < 2; mt++)
#pragma unroll
                for (int nt = 0; nt < 4; nt++) {
                    mma8(acc[mt][nt], al[mt], bh[nt]);
                    mma8(acc[mt][nt], ah[mt], bl[nt]);
                    mma8(acc[mt][nt], ah[mt], bh[nt]);
                }
        }
    }
    float* dst = g_logits_p + (size_t)kc * NTOK * NEXP;
#pragma unroll
    for (int mt = 0; mt < 2; mt++)
#pragma unroll
        for (int nt = 0; nt < 4; nt++)
#pragma unroll
            for (int r = 0; r < 4; r++) {
                int row = wm * 32 + mt * 16 + gq + ((r & 2) ? 8 : 0);
                int col = wn * 32 + nt * 8 + tq * 2 + (r & 1);
                dst[(size_t)(m0 + row) * NEXP + col] = acc[mt][nt][r];
            }
}

// ================= router softmax + top-6 + dispatch =================
__global__ void k_init() {
    if (threadIdx.x < NEXP) g_counts[threadIdx.x] = 0;
}

__global__ void k_router() {
    int warp = threadIdx.x >> 5, lane = threadIdx.x & 31;
    int t = blockIdx.x * 8 + warp;
    float v0 = 0.0f, v1 = 0.0f;
#pragma unroll
    for (int c = 0; c < RKC; c++) {
        v0 += g_logits_p[(size_t)c * NTOK * NEXP + t * NEXP + lane];
        v1 += g_logits_p[(size_t)c * NTOK * NEXP + t * NEXP + 32 + lane];
    }
    float m = fmaxf(v0, v1);
#pragma unroll
    for (int s = 16; s > 0; s >>= 1) m = fmaxf(m, __shfl_xor_sync(0xffffffffu, m, s));
    float e0 = expf(v0 - m), e1 = expf(v1 - m);
    float sum = e0 + e1;
#pragma unroll
    for (int s = 16; s > 0; s >>= 1) sum += __shfl_xor_sync(0xffffffffu, sum, s);
    float inv = 1.0f / sum;
    float p0 = e0 * inv, p1 = e1 * inv;

#pragma unroll
    for (int k = 0; k < TOPK; k++) {
        float bv; int bi;
        if (p0 >= p1) { bv = p0; bi = lane; } else { bv = p1; bi = lane + 32; }
#pragma unroll
        for (int s = 16; s > 0; s >>= 1) {
            float ov = __shfl_xor_sync(0xffffffffu, bv, s);
            int   oi = __shfl_xor_sync(0xffffffffu, bi, s);
            if (ov > bv || (ov == bv && oi < bi)) { bv = ov; bi = oi; }
        }
        if (lane == 0) {
            int pos = atomicAdd(&g_counts[bi], 1);
            if (pos < CAP) {
                g_buf_tok[bi * CAP + pos] = t;
                g_buf_w[bi * CAP + pos] = bv;
            }
        }
        if (bi < 32) { if (lane == bi) p0 = -1.0f; }
        else         { if (lane == bi - 32) p1 = -1.0f; }
    }
}

// ================= launch =================
extern "C" void kernel_launch(void* const* d_in, const int* in_sizes, int n_in,
                              void* d_out, int out_size) {
    const float* x   = (const float*)d_in[0];
    const float* gw  = (const float*)d_in[1];
    const float* gup = (const float*)d_in[2];
    const float* dwn = (const float*)d_in[3];
    const float* sgw = (const float*)d_in[4];
    const float* suw = (const float*)d_in[5];
    const float* sdw = (const float*)d_in[6];
    float* out = (float*)d_out;

    float *p_hid, *p_shid;
    cudaGetSymbolAddress((void**)&p_hid,  g_hid);
    cudaGetSymbolAddress((void**)&p_shid, g_shid);

    cudaFuncSetAttribute(k_swiglu<128,1,0,0>, cudaFuncAttributeMaxDynamicSharedMemorySize, SWIGLU_SMEM);
    cudaFuncSetAttribute(k_swiglu<64,0,1,1>,  cudaFuncAttributeMaxDynamicSharedMemorySize, SWIGLU_SMEM);
    cudaFuncSetAttribute(k_gemm<128,1,0,0>,   cudaFuncAttributeMaxDynamicSharedMemorySize, GEMM_SMEM);
    cudaFuncSetAttribute(k_gemm<64,0,1,1>,    cudaFuncAttributeMaxDynamicSharedMemorySize, GEMM_SMEM);

    k_init<<<1, 64>>>();
    // router: near-fp32 logits (K-split x4, deterministic reduce in k_router)
    k_router_gemm<<<dim3(RKC, NTOK / 64), RTH>>>(x, gw);
    k_router<<<NTOK / 8, 256>>>();

    // shared experts: fused SwiGLU up ([N,K] weights), then down -> out (plain store covers out)
    k_swiglu<128,1,0,0><<<dim3(SIDIM / 128, NTOK / 128), NTH, SWIGLU_SMEM>>>(
        x, sgw, suw, p_shid, HDIM, 0, SIDIM, 0, 0);
    k_gemm<128,1,0,0><<<dim3(HDIM / 128, NTOK / 128), NTH, GEMM_SMEM>>>(
        p_shid, sdw, out, SIDIM, 0, HDIM, 0, 0);

    // routed experts (64-row M blocks to cut capacity padding):
    k_swiglu<64,0,1,1><<<dim3(IDIM / 128, CAP / 64, NEXP), NTH, SWIGLU_SMEM>>>(
        x, gup, gup + IDIM, p_hid, HDIM, TWOI, IDIM, (long)HDIM * TWOI, (long)CAP * IDIM);
    k_gemm<64,0,1,1><<<dim3(HDIM / 128, CAP / 64, NEXP), NTH, GEMM_SMEM>>>(
        p_hid, dwn, out, IDIM, HDIM, HDIM, (long)CAP * IDIM, (long)IDIM * HDIM);
}

// round 15
// speedup vs baseline: 1.2477x; 1.2477x over previous
#include <cuda_runtime.h>
#include <cuda_fp16.h>
#include <math.h>
#include <stdint.h>

// ---------------- problem constants ----------------
#define NTOK   2048
#define NEXP   64
#define TOPK   6
#define CAP    512
#define HDIM   2048
#define IDIM   768
#define TWOI   1536
#define SIDIM  1536

// ---------------- tile config ----------------
#define BK   32              // k per slab (halfs)
#define NTH  256             // 8 warps
#define RSA  80              // [row][k] tile row stride BYTES (32 halfs + 16 pad)
#define RSB  272             // [k][n] tile row stride BYTES (128 halfs + 8 pad)
#define TSLOT 10240          // bytes per tile slot
#define SWIGLU_SMEM (12 * TSLOT)  // 4-slot ring x (A,G,U) = 122880 B
#define GEMM_SMEM   (16 * TSLOT)  // 8-slot ring x (A,B)   = 163840 B

// router K-split
#define RKC 4
#define RKLEN (HDIM / RKC)   // 512

// ---------------- scratch ----------------
__device__ int   g_counts[NEXP];
__device__ int   g_buf_tok[NEXP * CAP];
__device__ float g_buf_w[NEXP * CAP];
__device__ int   g_tok_slot[NTOK * TOPK];            // token -> e*CAP+pos (inverse map)
__device__ float g_logits_p[RKC * NTOK * NEXP];
__device__ float g_hid[(size_t)NEXP * CAP * IDIM];
__device__ float g_shid[(size_t)NTOK * SIDIM];
__device__ float g_eo[(size_t)NEXP * CAP * HDIM];    // routed down outputs (268 MB)

// ---------------- helpers ----------------
__device__ __forceinline__ uint32_t smem_u32(const void* p) {
    uint32_t a;
    asm("{ .reg .u64 t; cvta.to.shared.u64 t, %1; cvt.u32.u64 %0, t; }" : "=r"(a) : "l"(p));
    return a;
}
__device__ __forceinline__ uint32_t pack2(float a, float b) {
    __half2 h = __floats2half2_rn(a, b);
    return *(uint32_t*)&h;
}
__device__ __forceinline__ void ldsm4(uint32_t r[4], uint32_t addr) {
    asm volatile("ldmatrix.sync.aligned.m8n8.x4.shared.b16 {%0,%1,%2,%3}, [%4];"
                 : "=r"(r[0]), "=r"(r[1]), "=r"(r[2]), "=r"(r[3]) : "r"(addr));
}
__device__ __forceinline__ void ldsm4t(uint32_t r[4], uint32_t addr) {
    asm volatile("ldmatrix.sync.aligned.m8n8.x4.trans.shared.b16 {%0,%1,%2,%3}, [%4];"
                 : "=r"(r[0]), "=r"(r[1]), "=r"(r[2]), "=r"(r[3]) : "r"(addr));
}
__device__ __forceinline__ void mma16(float c[4], const uint32_t a[4], const uint32_t b[2]) {
    asm volatile(
        "mma.sync.aligned.m16n8k16.row.col.f32.f16.f16.f32 "
        "{%0,%1,%2,%3}, {%4,%5,%6,%7}, {%8,%9}, {%0,%1,%2,%3};"
        : "+f"(c[0]), "+f"(c[1]), "+f"(c[2]), "+f"(c[3])
        : "r"(a[0]), "r"(a[1]), "r"(a[2]), "r"(a[3]), "r"(b[0]), "r"(b[1]));
}
__device__ __forceinline__ unsigned f2tf(float x) {
    unsigned y;
    asm("cvt.rna.tf32.f32 %0, %1;" : "=r"(y) : "f"(x));
    return y;
}
__device__ __forceinline__ void mma8(float c[4], const unsigned a[4], const unsigned b[2]) {
    asm volatile(
        "mma.sync.aligned.m16n8k8.row.col.f32.tf32.tf32.f32 "
        "{%0,%1,%2,%3}, {%4,%5,%6,%7}, {%8,%9}, {%0,%1,%2,%3};"
        : "+f"(c[0]), "+f"(c[1]), "+f"(c[2]), "+f"(c[3])
        : "r"(a[0]), "r"(a[1]), "r"(a[2]), "r"(a[3]), "r"(b[0]), "r"(b[1]));
}
__device__ __forceinline__ float silu_f(float v) { return v / (1.0f + expf(-v)); }

// ldmatrix per-lane byte offsets:
#define LM_A(lane)  (((((lane) >> 3) & 1) * 8 + ((lane) & 7)) * RSA + ((lane) >> 4) * 16)
#define LM_BN(lane) ((((lane) >> 4) * 8 + ((lane) & 7)) * RSA + (((lane) >> 3) & 1) * 16)
#define LM_BT(lane) (((((lane) >> 3) & 1) * 8 + ((lane) & 7)) * RSB + ((lane) >> 4) * 16)

// ================= fused SwiGLU up-projection (fp16, BK=32, 4-slot ring) =================
template<int BNK, int EXPERT, int GATHER>
__global__ __launch_bounds__(NTH) void k_swiglu(
    const float* __restrict__ Abase, const float* __restrict__ Bg0,
    const float* __restrict__ Bu0, float* __restrict__ C,
    int Kd, int ldb, int ldc, long sB, long sC)
{
    extern __shared__ __align__(16) unsigned char smraw[];
    __shared__ int s_tok[128];

    const int tid = threadIdx.x;
    const int warp = tid >> 5, lane = tid & 31;
    const int wm = warp >> 2, wn = warp & 3;
    const int gq = lane >> 2, tq = lane & 3;
    const int m0 = blockIdx.y * 128, n0 = blockIdx.x * 128;

    int e = 0, cnt = 0x40000000;
    if (EXPERT) {
        e = blockIdx.z;
        cnt = g_counts[e];
        if (m0 >= cnt) return;
    }
    if (GATHER) {
        if (tid < 128) {
            int p = m0 + tid;
            s_tok[tid] = (p < cnt) ? g_buf_tok[e * CAP + p] : 0;
        }
        __syncthreads();
    }

    const uint32_t smb = smem_u32(smraw);

    const float* pa[4];
    uint32_t stA[4];
#pragma unroll
    for (int j = 0; j < 4; j++) {
        int idx = tid + j * NTH;
        int m = idx >> 3, k8 = idx & 7;
        if (GATHER) pa[j] = Abase + (size_t)s_tok[m] * Kd + k8 * 4;
        else        pa[j] = Abase + (size_t)(m0 + m) * Kd + k8 * 4;
        stA[j] = (uint32_t)(m * RSA + k8 * 8);
    }
    const float* pg[4]; const float* pu[4];
    uint32_t stB[4];
#pragma unroll
    for (int j = 0; j < 4; j++) {
        int idx = tid + j * NTH;
        if (BNK) {
            int n = idx >> 3, k8 = idx & 7;
            pg[j] = Bg0 + (EXPERT ? (size_t)e * sB : 0) + (size_t)(n0 + n) * Kd + k8 * 4;
            pu[j] = Bu0 + (EXPERT ? (size_t)e * sB : 0) + (size_t)(n0 + n) * Kd + k8 * 4;
            stB[j] = (uint32_t)(n * RSA + k8 * 8);
        } else {
            int k = idx >> 5, n8 = idx & 31;
            pg[j] = Bg0 + (EXPERT ? (size_t)e * sB : 0) + (size_t)k * ldb + n0 + n8 * 4;
            pu[j] = Bu0 + (EXPERT ? (size_t)e * sB : 0) + (size_t)k * ldb + n0 + n8 * 4;
            stB[j] = (uint32_t)(k * RSB + n8 * 8);
        }
    }
    const long bumpB = BNK ? (long)BK : (long)BK * ldb;

    float4 ra[4], rg[4], ru[4];
    auto LDG = [&]() {
#pragma unroll
        for (int j = 0; j < 4; j++) { ra[j] = *(const float4*)pa[j]; pa[j] += BK; }
#pragma unroll
        for (int j = 0; j < 4; j++) { rg[j] = *(const float4*)pg[j]; pg[j] += bumpB; }
#pragma unroll
        for (int j = 0; j < 4; j++) { ru[j] = *(const float4*)pu[j]; pu[j] += bumpB; }
    };
    auto STS = [&](int slot) {
        uint32_t aT = smb + slot * TSLOT;
        uint32_t gT = smb + 4 * TSLOT + slot * TSLOT;
        uint32_t uT = smb + 8 * TSLOT + slot * TSLOT;
#pragma unroll
        for (int j = 0; j < 4; j++) {
            uint2 v = make_uint2(pack2(ra[j].x, ra[j].y), pack2(ra[j].z, ra[j].w));
            asm volatile("st.shared.v2.u32 [%0], {%1, %2};" :: "r"(aT + stA[j]), "r"(v.x), "r"(v.y));
        }
#pragma unroll
        for (int j = 0; j < 4; j++) {
            uint2 vg = make_uint2(pack2(rg[j].x, rg[j].y), pack2(rg[j].z, rg[j].w));
            asm volatile("st.shared.v2.u32 [%0], {%1, %2};" :: "r"(gT + stB[j]), "r"(vg.x), "r"(vg.y));
            uint2 vu = make_uint2(pack2(ru[j].x, ru[j].y), pack2(ru[j].z, ru[j].w));
            asm volatile("st.shared.v2.u32 [%0], {%1, %2};" :: "r"(uT + stB[j]), "r"(vu.x), "r"(vu.y));
        }
    };

    uint32_t aOff[4];
#pragma unroll
    for (int mt = 0; mt < 4; mt++) aOff[mt] = (uint32_t)((wm * 64 + mt * 16) * RSA) + LM_A(lane);
    uint32_t bOff[2];
#pragma unroll
    for (int p = 0; p < 2; p++)
        bOff[p] = BNK ? (uint32_t)((wn * 32 + p * 16) * RSA) + LM_BN(lane)
                      : (uint32_t)((wn * 32 + p * 16) * 2) + LM_BT(lane);

    float accg[4][4][4], accu[4][4][4];
#pragma unroll
    for (int mt = 0; mt < 4; mt++)
#pragma unroll
        for (int nt = 0; nt < 4; nt++)
#pragma unroll
            for (int r = 0; r < 4; r++) { accg[mt][nt][r] = 0.0f; accu[mt][nt][r] = 0.0f; }

    auto COMPUTE = [&](int slot) {
        uint32_t aT = smb + slot * TSLOT;
        uint32_t gT = smb + 4 * TSLOT + slot * TSLOT;
        uint32_t uT = smb + 8 * TSLOT + slot * TSLOT;
#pragma unroll
        for (int kh = 0; kh < 2; kh++) {
            const uint32_t kA = kh * 32;
            const uint32_t kB = BNK ? (uint32_t)(kh * 32) : (uint32_t)(kh * 16 * RSB);
            uint32_t af[4][4];
#pragma unroll
            for (int mt = 0; mt < 4; mt++) ldsm4(af[mt], aT + aOff[mt] + kA);
            uint32_t bg[4][2], bu[4][2];
#pragma unroll
            for (int p = 0; p < 2; p++) {
                uint32_t t[4];
                if (BNK) ldsm4(t, gT + bOff[p] + kB); else ldsm4t(t, gT + bOff[p] + kB);
                bg[2 * p][0] = t[0]; bg[2 * p][1] = t[1];
                bg[2 * p + 1][0] = t[2]; bg[2 * p + 1][1] = t[3];
                if (BNK) ldsm4(t, uT + bOff[p] + kB); else ldsm4t(t, uT + bOff[p] + kB);
                bu[2 * p][0] = t[0]; bu[2 * p][1] = t[1];
                bu[2 * p + 1][0] = t[2]; bu[2 * p + 1][1] = t[3];
            }
#pragma unroll
            for (int mt = 0; mt < 4; mt++)
#pragma unroll
                for (int nt = 0; nt < 4; nt++) {
                    mma16(accg[mt][nt], af[mt], bg[nt]);
                    mma16(accu[mt][nt], af[mt], bu[nt]);
                }
        }
    };

    const int nslab = Kd / BK;
    LDG(); STS(0);
    LDG(); STS(1);

    for (int t = 0; t < nslab / 2; t++) {
        __syncthreads();
        const int s0 = 2 * t, s1 = 2 * t + 1;
        const bool pf0 = (s0 + 2 < nslab), pf1 = (s1 + 2 < nslab);
        if (pf0) LDG();
        COMPUTE(s0 & 3);
        if (pf0) STS((s0 + 2) & 3);
        if (pf1) LDG();
        COMPUTE(s1 & 3);
        if (pf1) STS((s1 + 2) & 3);
    }

    // ---- epilogue: silu(g)*u ----
#pragma unroll
    for (int mt = 0; mt < 4; mt++)
#pragma unroll
        for (int nt = 0; nt < 4; nt++)
#pragma unroll
            for (int r = 0; r < 4; r++) {
                int row = wm * 64 + mt * 16 + gq + ((r & 2) ? 8 : 0);
                int col = wn * 32 + nt * 8 + tq * 2 + (r & 1);
                int gm = m0 + row;
                if (EXPERT && gm >= cnt) continue;
                float g = accg[mt][nt][r], u = accu[mt][nt][r];
                float* dst = C + (EXPERT ? (size_t)e * sC : 0);
                dst[(size_t)gm * ldc + n0 + col] = silu_f(g) * u;
            }
}

// ================= down GEMM (fp16, BK=32, 8-slot ring, sync per 4 slabs) =================
// SCATTER=1: routed path — plain store of acc*w into g_eo at row e*CAP+gm (no atomics).
template<int BNK, int EXPERT, int SCATTER>
__global__ __launch_bounds__(NTH) void k_gemm(
    const float* __restrict__ Abase, const float* __restrict__ Bbase,
    float* __restrict__ C, int Kd, int ldb, int ldc,
    long sA, long sB)
{
    extern __shared__ __align__(16) unsigned char smraw[];
    __shared__ float s_w[128];

    const int tid = threadIdx.x;
    const int warp = tid >> 5, lane = tid & 31;
    const int wm = warp >> 2, wn = warp & 3;
    const int gq = lane >> 2, tq = lane & 3;
    const int m0 = blockIdx.y * 128, n0 = blockIdx.x * 128;

    int e = 0, cnt = 0x40000000;
    if (EXPERT) {
        e = blockIdx.z;
        cnt = g_counts[e];
        if (m0 >= cnt) return;
    }
    if (SCATTER) {
        if (tid < 128) {
            int p = m0 + tid;
            s_w[tid] = (p < cnt) ? g_buf_w[e * CAP + p] : 0.0f;
        }
        __syncthreads();
    }

    const uint32_t smb = smem_u32(smraw);

    const float* pa[4];
    uint32_t stA[4];
#pragma unroll
    for (int j = 0; j < 4; j++) {
        int idx = tid + j * NTH;
        int m = idx >> 3, k8 = idx & 7;
        pa[j] = Abase + (EXPERT ? (size_t)e * sA : 0) + (size_t)(m0 + m) * Kd + k8 * 4;
        stA[j] = (uint32_t)(m * RSA + k8 * 8);
    }
    const float* pb[4];
    uint32_t stB[4];
#pragma unroll
    for (int j = 0; j < 4; j++) {
        int idx = tid + j * NTH;
        if (BNK) {
            int n = idx >> 3, k8 = idx & 7;
            pb[j] = Bbase + (EXPERT ? (size_t)e * sB : 0) + (size_t)(n0 + n) * Kd + k8 * 4;
            stB[j] = (uint32_t)(n * RSA + k8 * 8);
        } else {
            int k = idx >> 5, n8 = idx & 31;
            pb[j] = Bbase + (EXPERT ? (size_t)e * sB : 0) + (size_t)k * ldb + n0 + n8 * 4;
            stB[j] = (uint32_t)(k * RSB + n8 * 8);
        }
    }
    const long bumpB = BNK ? (long)BK : (long)BK * ldb;

    float4 ra[4], rb[4];
    auto LDG = [&]() {
#pragma unroll
        for (int j = 0; j < 4; j++) { ra[j] = *(const float4*)pa[j]; pa[j] += BK; }
#pragma unroll
        for (int j = 0; j < 4; j++) { rb[j] = *(const float4*)pb[j]; pb[j] += bumpB; }
    };
    auto STS = [&](int slot) {
        uint32_t aT = smb + slot * TSLOT;
        uint32_t bT = smb + 8 * TSLOT + slot * TSLOT;
#pragma unroll
        for (int j = 0; j < 4; j++) {
            uint2 v = make_uint2(pack2(ra[j].x, ra[j].y), pack2(ra[j].z, ra[j].w));
            asm volatile("st.shared.v2.u32 [%0], {%1, %2};" :: "r"(aT + stA[j]), "r"(v.x), "r"(v.y));
        }
#pragma unroll
        for (int j = 0; j < 4; j++) {
            uint2 v = make_uint2(pack2(rb[j].x, rb[j].y), pack2(rb[j].z, rb[j].w));
            asm volatile("st.shared.v2.u32 [%0], {%1, %2};" :: "r"(bT + stB[j]), "r"(v.x), "r"(v.y));
        }
    };

    uint32_t aOff[4];
#pragma unroll
    for (int mt = 0; mt < 4; mt++) aOff[mt] = (uint32_t)((wm * 64 + mt * 16) * RSA) + LM_A(lane);
    uint32_t bOff[2];
#pragma unroll
    for (int p = 0; p < 2; p++)
        bOff[p] = BNK ? (uint32_t)((wn * 32 + p * 16) * RSA) + LM_BN(lane)
                      : (uint32_t)((wn * 32 + p * 16) * 2) + LM_BT(lane);

    float acc[4][4][4];
#pragma unroll
    for (int mt = 0; mt < 4; mt++)
#pragma unroll
        for (int nt = 0; nt < 4; nt++)
#pragma unroll
            for (int r = 0; r < 4; r++) acc[mt][nt][r] = 0.0f;

    auto COMPUTE = [&](int slot) {
        uint32_t aT = smb + slot * TSLOT;
        uint32_t bT = smb + 8 * TSLOT + slot * TSLOT;
#pragma unroll
        for (int kh = 0; kh < 2; kh++) {
            const uint32_t kA = kh * 32;
            const uint32_t kB = BNK ? (uint32_t)(kh * 32) : (uint32_t)(kh * 16 * RSB);
            uint32_t af[4][4];
#pragma unroll
            for (int mt = 0; mt < 4; mt++) ldsm4(af[mt], aT + aOff[mt] + kA);
            uint32_t bf[4][2];
#pragma unroll
            for (int p = 0; p < 2; p++) {
                uint32_t t[4];
                if (BNK) ldsm4(t, bT + bOff[p] + kB); else ldsm4t(t, bT + bOff[p] + kB);
                bf[2 * p][0] = t[0]; bf[2 * p][1] = t[1];
                bf[2 * p + 1][0] = t[2]; bf[2 * p + 1][1] = t[3];
            }
#pragma unroll
            for (int mt = 0; mt < 4; mt++)
#pragma unroll
                for (int nt = 0; nt < 4; nt++)
                    mma16(acc[mt][nt], af[mt], bf[nt]);
        }
    };

    const int nslab = Kd / BK;          // 48 or 24: divisible by 4
    LDG(); STS(0);
    LDG(); STS(1);
    LDG(); STS(2);
    LDG(); STS(3);

    for (int t = 0; t < nslab / 4; t++) {
        __syncthreads();
#pragma unroll
        for (int i = 0; i < 4; i++) {
            const int s = 4 * t + i;
            const bool pf = (s + 4 < nslab);
            if (pf) LDG();
            COMPUTE(s & 7);
            if (pf) STS((s + 4) & 7);
        }
    }

#pragma unroll
    for (int mt = 0; mt < 4; mt++)
#pragma unroll
        for (int nt = 0; nt < 4; nt++)
#pragma unroll
            for (int r = 0; r < 4; r++) {
                int row = wm * 64 + mt * 16 + gq + ((r & 2) ? 8 : 0);
                int col = wn * 32 + nt * 8 + tq * 2 + (r & 1);
                int gm = m0 + row;
                if (EXPERT && gm >= cnt) continue;
                if (SCATTER) {
                    // plain store into per-(expert,slot) buffer; combined later
                    C[((size_t)e * CAP + gm) * ldc + n0 + col] = acc[mt][nt][r] * s_w[row];
                } else {
                    C[(size_t)gm * ldc + n0 + col] = acc[mt][nt][r];
                }
            }
}

// ================= combine: out[t] += sum_k eo[slot(t,k)] (fixed order) =================
__global__ __launch_bounds__(512) void k_combine(float* __restrict__ out) {
    const int t = blockIdx.x;
    const int c4 = threadIdx.x;                    // 0..511 -> float4 col
    int slots[TOPK];
#pragma unroll
    for (int k = 0; k < TOPK; k++) slots[k] = g_tok_slot[t * TOPK + k];
    float4 acc = ((const float4*)out)[(size_t)t * (HDIM / 4) + c4];
#pragma unroll
    for (int k = 0; k < TOPK; k++) {
        float4 v = ((const float4*)g_eo)[(size_t)slots[k] * (HDIM / 4) + c4];
        acc.x += v.x; acc.y += v.y; acc.z += v.z; acc.w += v.w;
    }
    ((float4*)out)[(size_t)t * (HDIM / 4) + c4] = acc;
}

// ================= router logits: 3xTF32, K-split x4 (near-fp32, exact top-k) =================
#define RTH 128
__global__ __launch_bounds__(RTH) void k_router_gemm(const float* __restrict__ A,
                                                     const float* __restrict__ B) {
    __shared__ float As[16][64 + 4];
    __shared__ float Bsm[16][64 + 4];
    int tid = threadIdx.x;
    int warp = tid >> 5, lane = tid & 31;
    int wm = warp >> 1, wn = warp & 1, gq = lane >> 2, tq = lane & 3;
    int m0 = blockIdx.y * 64;
    int kc = blockIdx.x;
    int kbase = kc * RKLEN;

    const float* Ab = A + (size_t)m0 * HDIM + kbase;
    const float* Bb = B + kbase;

    float acc[2][4][4];
#pragma unroll
    for (int mt = 0; mt < 2; mt++)
#pragma unroll
        for (int nt = 0; nt < 4; nt++)
#pragma unroll
            for (int r = 0; r < 4; r++) acc[mt][nt][r] = 0.0f;

    for (int k0 = 0; k0 < RKLEN; k0 += 16) {
        __syncthreads();
#pragma unroll
        for (int j = 0; j < 2; j++) {
            int it = tid + j * RTH;
            int r = it >> 2, c4 = it & 3;
            float4 va = *(const float4*)(Ab + (size_t)r * HDIM + k0 + c4 * 4);
            As[c4 * 4 + 0][r] = va.x; As[c4 * 4 + 1][r] = va.y;
            As[c4 * 4 + 2][r] = va.z; As[c4 * 4 + 3][r] = va.w;
            float4 vb = *(const float4*)(Bb + (size_t)r * HDIM + k0 + c4 * 4);
            Bsm[c4 * 4 + 0][r] = vb.x; Bsm[c4 * 4 + 1][r] = vb.y;
            Bsm[c4 * 4 + 2][r] = vb.z; Bsm[c4 * 4 + 3][r] = vb.w;
        }
        __syncthreads();
#pragma unroll
        for (int kk = 0; kk < 16; kk += 8) {
            float af[2][4], bfv[4][2];
#pragma unroll
            for (int mt = 0; mt < 2; mt++) {
                int rb = wm * 32 + mt * 16;
                af[mt][0] = As[kk + tq    ][rb + gq    ];
                af[mt][1] = As[kk + tq    ][rb + gq + 8];
                af[mt][2] = As[kk + tq + 4][rb + gq    ];
                af[mt][3] = As[kk + tq + 4][rb + gq + 8];
            }
#pragma unroll
            for (int nt = 0; nt < 4; nt++) {
                int cb = wn * 32 + nt * 8 + gq;
                bfv[nt][0] = Bsm[kk + tq    ][cb];
                bfv[nt][1] = Bsm[kk + tq + 4][cb];
            }
            unsigned ah[2][4], al[2][4], bh[4][2], bl[4][2];
#pragma unroll
            for (int mt = 0; mt < 2; mt++)
#pragma unroll
                for (int i = 0; i < 4; i++) {
                    ah[mt][i] = f2tf(af[mt][i]);
                    al[mt][i] = f2tf(af[mt][i] - __uint_as_float(ah[mt][i]));
                }
#pragma unroll
            for (int nt = 0; nt < 4; nt++)
#pragma unroll
                for (int i = 0; i < 2; i++) {
                    bh[nt][i] = f2tf(bfv[nt][i]);
                    bl[nt][i] = f2tf(bfv[nt][i] - __uint_as_float(bh[nt][i]));
                }
#pragma unroll
            for (int mt = 0; mt < 2; mt++)
#pragma unroll
                for (int nt = 0; nt < 4; nt++) {
                    mma8(acc[mt][nt], al[mt], bh[nt]);
                    mma8(acc[mt][nt], ah[mt], bl[nt]);
                    mma8(acc[mt][nt], ah[mt], bh[nt]);
                }
        }
    }
    float* dst = g_logits_p + (size_t)kc * NTOK * NEXP;
#pragma unroll
    for (int mt = 0; mt < 2; mt++)
#pragma unroll
        for (int nt = 0; nt < 4; nt++)
#pragma unroll
            for (int r = 0; r < 4; r++) {
                int row = wm * 32 + mt * 16 + gq + ((r & 2) ? 8 : 0);
                int col = wn * 32 + nt * 8 + tq * 2 + (r & 1);
                dst[(size_t)(m0 + row) * NEXP + col] = acc[mt][nt][r];
            }
}

// ================= router softmax + top-6 + dispatch =================
__global__ void k_init() {
    if (threadIdx.x < NEXP) g_counts[threadIdx.x] = 0;
}

__global__ void k_router() {
    int warp = threadIdx.x >> 5, lane = threadIdx.x & 31;
    int t = blockIdx.x * 8 + warp;
    float v0 = 0.0f, v1 = 0.0f;
#pragma unroll
    for (int c = 0; c < RKC; c++) {
        v0 += g_logits_p[(size_t)c * NTOK * NEXP + t * NEXP + lane];
        v1 += g_logits_p[(size_t)c * NTOK * NEXP + t * NEXP + 32 + lane];
    }
    float m = fmaxf(v0, v1);
#pragma unroll
    for (int s = 16; s > 0; s >>= 1) m = fmaxf(m, __shfl_xor_sync(0xffffffffu, m, s));
    float e0 = expf(v0 - m), e1 = expf(v1 - m);
    float sum = e0 + e1;
#pragma unroll
    for (int s = 16; s > 0; s >>= 1) sum += __shfl_xor_sync(0xffffffffu, sum, s);
    float inv = 1.0f / sum;
    float p0 = e0 * inv, p1 = e1 * inv;

#pragma unroll
    for (int k = 0; k < TOPK; k++) {
        float bv; int bi;
        if (p0 >= p1) { bv = p0; bi = lane; } else { bv = p1; bi = lane + 32; }
#pragma unroll
        for (int s = 16; s > 0; s >>= 1) {
            float ov = __shfl_xor_sync(0xffffffffu, bv, s);
            int   oi = __shfl_xor_sync(0xffffffffu, bi, s);
            if (ov > bv || (ov == bv && oi < bi)) { bv = ov; bi = oi; }
        }
        if (lane == 0) {
            int pos = atomicAdd(&g_counts[bi], 1);
            if (pos < CAP) {
                g_buf_tok[bi * CAP + pos] = t;
                g_buf_w[bi * CAP + pos] = bv;
                g_tok_slot[t * TOPK + k] = bi * CAP + pos;   // inverse map for combine
            }
        }
        if (bi < 32) { if (lane == bi) p0 = -1.0f; }
        else         { if (lane == bi - 32) p1 = -1.0f; }
    }
}

// ================= launch =================
extern "C" void kernel_launch(void* const* d_in, const int* in_sizes, int n_in,
                              void* d_out, int out_size) {
    const float* x   = (const float*)d_in[0];
    const float* gw  = (const float*)d_in[1];
    const float* gup = (const float*)d_in[2];
    const float* dwn = (const float*)d_in[3];
    const float* sgw = (const float*)d_in[4];
    const float* suw = (const float*)d_in[5];
    const float* sdw = (const float*)d_in[6];
    float* out = (float*)d_out;

    float *p_hid, *p_shid, *p_eo;
    cudaGetSymbolAddress((void**)&p_hid,  g_hid);
    cudaGetSymbolAddress((void**)&p_shid, g_shid);
    cudaGetSymbolAddress((void**)&p_eo,   g_eo);

    cudaFuncSetAttribute(k_swiglu<1,0,0>, cudaFuncAttributeMaxDynamicSharedMemorySize, SWIGLU_SMEM);
    cudaFuncSetAttribute(k_swiglu<0,1,1>, cudaFuncAttributeMaxDynamicSharedMemorySize, SWIGLU_SMEM);
    cudaFuncSetAttribute(k_gemm<1,0,0>,   cudaFuncAttributeMaxDynamicSharedMemorySize, GEMM_SMEM);
    cudaFuncSetAttribute(k_gemm<0,1,1>,   cudaFuncAttributeMaxDynamicSharedMemorySize, GEMM_SMEM);

    k_init<<<1, 64>>>();
    // router: near-fp32 logits (K-split x4, deterministic reduce in k_router)
    k_router_gemm<<<dim3(RKC, NTOK / 64), RTH>>>(x, gw);
    k_router<<<NTOK / 8, 256>>>();

    // shared experts: fused SwiGLU up ([N,K] weights), then down -> out (plain store covers out)
    k_swiglu<1,0,0><<<dim3(SIDIM / 128, NTOK / 128), NTH, SWIGLU_SMEM>>>(
        x, sgw, suw, p_shid, HDIM, 0, SIDIM, 0, 0);
    k_gemm<1,0,0><<<dim3(HDIM / 128, NTOK / 128), NTH, GEMM_SMEM>>>(
        p_shid, sdw, out, SIDIM, 0, HDIM, 0, 0);

    // routed experts: gate_up (gathered A), down -> g_eo (plain stores, weighted)
    k_swiglu<0,1,1><<<dim3(IDIM / 128, CAP / 128, NEXP), NTH, SWIGLU_SMEM>>>(
        x, gup, gup + IDIM, p_hid, HDIM, TWOI, IDIM, (long)HDIM * TWOI, (long)CAP * IDIM);
    k_gemm<0,1,1><<<dim3(HDIM / 128, CAP / 128, NEXP), NTH, GEMM_SMEM>>>(
        p_hid, dwn, p_eo, IDIM, HDIM, HDIM, (long)CAP * IDIM, (long)IDIM * HDIM);

    // gather-combine: out[t] += sum of the token's 6 expert outputs (fixed order)
    k_combine<<<NTOK, 512>>>(out);
}

// round 16
// speedup vs baseline: 1.2674x; 1.0158x over previous
#include <cuda_runtime.h>
#include <cuda_fp16.h>
#include <math.h>
#include <stdint.h>

// ---------------- problem constants ----------------
#define NTOK   2048
#define NEXP   64
#define TOPK   6
#define CAP    512
#define HDIM   2048
#define IDIM   768
#define TWOI   1536
#define SIDIM  1536

// ---------------- tile config ----------------
#define BK   32              // k per slab (halfs)
#define NTH  256             // 8 warps
#define RSA  80              // [row][k] tile row stride BYTES (32 halfs + 16 pad)
#define RSB  272             // [k][n] tile row stride BYTES (128 halfs + 8 pad)
#define TSLOT 10240          // bytes per tile slot
#define SWIGLU_SMEM (12 * TSLOT)  // 4-slot ring x (A,G,U) = 122880 B
#define GEMM_SMEM   (16 * TSLOT)  // 8-slot ring x (A,B)   = 163840 B

// router K-split
#define RKC 4
#define RKLEN (HDIM / RKC)   // 512

// ---------------- scratch ----------------
__device__ int    g_counts[NEXP];
__device__ int    g_buf_tok[NEXP * CAP];
__device__ float  g_buf_w[NEXP * CAP];
__device__ float  g_logits_p[RKC * NTOK * NEXP];
__device__ __half g_hid[(size_t)NEXP * CAP * IDIM];   // fp16 intermediates (50 MB)
__device__ __half g_shid[(size_t)NTOK * SIDIM];       // fp16 (6.3 MB)

// ---------------- helpers ----------------
__device__ __forceinline__ uint32_t smem_u32(const void* p) {
    uint32_t a;
    asm("{ .reg .u64 t; cvta.to.shared.u64 t, %1; cvt.u32.u64 %0, t; }" : "=r"(a) : "l"(p));
    return a;
}
__device__ __forceinline__ uint32_t pack2(float a, float b) {
    __half2 h = __floats2half2_rn(a, b);
    return *(uint32_t*)&h;
}
__device__ __forceinline__ void ldsm4(uint32_t r[4], uint32_t addr) {
    asm volatile("ldmatrix.sync.aligned.m8n8.x4.shared.b16 {%0,%1,%2,%3}, [%4];"
                 : "=r"(r[0]), "=r"(r[1]), "=r"(r[2]), "=r"(r[3]) : "r"(addr));
}
__device__ __forceinline__ void ldsm4t(uint32_t r[4], uint32_t addr) {
    asm volatile("ldmatrix.sync.aligned.m8n8.x4.trans.shared.b16 {%0,%1,%2,%3}, [%4];"
                 : "=r"(r[0]), "=r"(r[1]), "=r"(r[2]), "=r"(r[3]) : "r"(addr));
}
__device__ __forceinline__ void mma16(float c[4], const uint32_t a[4], const uint32_t b[2]) {
    asm volatile(
        "mma.sync.aligned.m16n8k16.row.col.f32.f16.f16.f32 "
        "{%0,%1,%2,%3}, {%4,%5,%6,%7}, {%8,%9}, {%0,%1,%2,%3};"
        : "+f"(c[0]), "+f"(c[1]), "+f"(c[2]), "+f"(c[3])
        : "r"(a[0]), "r"(a[1]), "r"(a[2]), "r"(a[3]), "r"(b[0]), "r"(b[1]));
}
__device__ __forceinline__ unsigned f2tf(float x) {
    unsigned y;
    asm("cvt.rna.tf32.f32 %0, %1;" : "=r"(y) : "f"(x));
    return y;
}
__device__ __forceinline__ void mma8(float c[4], const unsigned a[4], const unsigned b[2]) {
    asm volatile(
        "mma.sync.aligned.m16n8k8.row.col.f32.tf32.tf32.f32 "
        "{%0,%1,%2,%3}, {%4,%5,%6,%7}, {%8,%9}, {%0,%1,%2,%3};"
        : "+f"(c[0]), "+f"(c[1]), "+f"(c[2]), "+f"(c[3])
        : "r"(a[0]), "r"(a[1]), "r"(a[2]), "r"(a[3]), "r"(b[0]), "r"(b[1]));
}
__device__ __forceinline__ float silu_f(float v) { return v / (1.0f + expf(-v)); }

// ldmatrix per-lane byte offsets:
#define LM_A(lane)  (((((lane) >> 3) & 1) * 8 + ((lane) & 7)) * RSA + ((lane) >> 4) * 16)
#define LM_BN(lane) ((((lane) >> 4) * 8 + ((lane) & 7)) * RSA + (((lane) >> 3) & 1) * 16)
#define LM_BT(lane) (((((lane) >> 3) & 1) * 8 + ((lane) & 7)) * RSB + ((lane) >> 4) * 16)

// ================= fused SwiGLU up-projection (fp16, BK=32, 4-slot ring) =================
// Output C is __half (intermediates). Numerics identical to fp32-store + rn-on-load.
template<int BNK, int EXPERT, int GATHER>
__global__ __launch_bounds__(NTH) void k_swiglu(
    const float* __restrict__ Abase, const float* __restrict__ Bg0,
    const float* __restrict__ Bu0, __half* __restrict__ C,
    int Kd, int ldb, int ldc, long sB, long sC)
{
    extern __shared__ __align__(16) unsigned char smraw[];
    __shared__ int s_tok[128];

    const int tid = threadIdx.x;
    const int warp = tid >> 5, lane = tid & 31;
    const int wm = warp >> 2, wn = warp & 3;
    const int gq = lane >> 2, tq = lane & 3;
    const int m0 = blockIdx.y * 128, n0 = blockIdx.x * 128;

    int e = 0, cnt = 0x40000000;
    if (EXPERT) {
        e = blockIdx.z;
        cnt = g_counts[e];
        if (m0 >= cnt) return;
    }
    if (GATHER) {
        if (tid < 128) {
            int p = m0 + tid;
            s_tok[tid] = (p < cnt) ? g_buf_tok[e * CAP + p] : 0;
        }
        __syncthreads();
    }

    const uint32_t smb = smem_u32(smraw);

    const float* pa[4];
    uint32_t stA[4];
#pragma unroll
    for (int j = 0; j < 4; j++) {
        int idx = tid + j * NTH;
        int m = idx >> 3, k8 = idx & 7;
        if (GATHER) pa[j] = Abase + (size_t)s_tok[m] * Kd + k8 * 4;
        else        pa[j] = Abase + (size_t)(m0 + m) * Kd + k8 * 4;
        stA[j] = (uint32_t)(m * RSA + k8 * 8);
    }
    const float* pg[4]; const float* pu[4];
    uint32_t stB[4];
#pragma unroll
    for (int j = 0; j < 4; j++) {
        int idx = tid + j * NTH;
        if (BNK) {
            int n = idx >> 3, k8 = idx & 7;
            pg[j] = Bg0 + (EXPERT ? (size_t)e * sB : 0) + (size_t)(n0 + n) * Kd + k8 * 4;
            pu[j] = Bu0 + (EXPERT ? (size_t)e * sB : 0) + (size_t)(n0 + n) * Kd + k8 * 4;
            stB[j] = (uint32_t)(n * RSA + k8 * 8);
        } else {
            int k = idx >> 5, n8 = idx & 31;
            pg[j] = Bg0 + (EXPERT ? (size_t)e * sB : 0) + (size_t)k * ldb + n0 + n8 * 4;
            pu[j] = Bu0 + (EXPERT ? (size_t)e * sB : 0) + (size_t)k * ldb + n0 + n8 * 4;
            stB[j] = (uint32_t)(k * RSB + n8 * 8);
        }
    }
    const long bumpB = BNK ? (long)BK : (long)BK * ldb;

    float4 ra[4], rg[4], ru[4];
    auto LDG = [&]() {
#pragma unroll
        for (int j = 0; j < 4; j++) { ra[j] = *(const float4*)pa[j]; pa[j] += BK; }
#pragma unroll
        for (int j = 0; j < 4; j++) { rg[j] = *(const float4*)pg[j]; pg[j] += bumpB; }
#pragma unroll
        for (int j = 0; j < 4; j++) { ru[j] = *(const float4*)pu[j]; pu[j] += bumpB; }
    };
    auto STS = [&](int slot) {
        uint32_t aT = smb + slot * TSLOT;
        uint32_t gT = smb + 4 * TSLOT + slot * TSLOT;
        uint32_t uT = smb + 8 * TSLOT + slot * TSLOT;
#pragma unroll
        for (int j = 0; j < 4; j++) {
            uint2 v = make_uint2(pack2(ra[j].x, ra[j].y), pack2(ra[j].z, ra[j].w));
            asm volatile("st.shared.v2.u32 [%0], {%1, %2};" :: "r"(aT + stA[j]), "r"(v.x), "r"(v.y));
        }
#pragma unroll
        for (int j = 0; j < 4; j++) {
            uint2 vg = make_uint2(pack2(rg[j].x, rg[j].y), pack2(rg[j].z, rg[j].w));
            asm volatile("st.shared.v2.u32 [%0], {%1, %2};" :: "r"(gT + stB[j]), "r"(vg.x), "r"(vg.y));
            uint2 vu = make_uint2(pack2(ru[j].x, ru[j].y), pack2(ru[j].z, ru[j].w));
            asm volatile("st.shared.v2.u32 [%0], {%1, %2};" :: "r"(uT + stB[j]), "r"(vu.x), "r"(vu.y));
        }
    };

    uint32_t aOff[4];
#pragma unroll
    for (int mt = 0; mt < 4; mt++) aOff[mt] = (uint32_t)((wm * 64 + mt * 16) * RSA) + LM_A(lane);
    uint32_t bOff[2];
#pragma unroll
    for (int p = 0; p < 2; p++)
        bOff[p] = BNK ? (uint32_t)((wn * 32 + p * 16) * RSA) + LM_BN(lane)
                      : (uint32_t)((wn * 32 + p * 16) * 2) + LM_BT(lane);

    float accg[4][4][4], accu[4][4][4];
#pragma unroll
    for (int mt = 0; mt < 4; mt++)
#pragma unroll
        for (int nt = 0; nt < 4; nt++)
#pragma unroll
            for (int r = 0; r < 4; r++) { accg[mt][nt][r] = 0.0f; accu[mt][nt][r] = 0.0f; }

    auto COMPUTE = [&](int slot) {
        uint32_t aT = smb + slot * TSLOT;
        uint32_t gT = smb + 4 * TSLOT + slot * TSLOT;
        uint32_t uT = smb + 8 * TSLOT + slot * TSLOT;
#pragma unroll
        for (int kh = 0; kh < 2; kh++) {
            const uint32_t kA = kh * 32;
            const uint32_t kB = BNK ? (uint32_t)(kh * 32) : (uint32_t)(kh * 16 * RSB);
            uint32_t af[4][4];
#pragma unroll
            for (int mt = 0; mt < 4; mt++) ldsm4(af[mt], aT + aOff[mt] + kA);
            uint32_t bg[4][2], bu[4][2];
#pragma unroll
            for (int p = 0; p < 2; p++) {
                uint32_t t[4];
                if (BNK) ldsm4(t, gT + bOff[p] + kB); else ldsm4t(t, gT + bOff[p] + kB);
                bg[2 * p][0] = t[0]; bg[2 * p][1] = t[1];
                bg[2 * p + 1][0] = t[2]; bg[2 * p + 1][1] = t[3];
                if (BNK) ldsm4(t, uT + bOff[p] + kB); else ldsm4t(t, uT + bOff[p] + kB);
                bu[2 * p][0] = t[0]; bu[2 * p][1] = t[1];
                bu[2 * p + 1][0] = t[2]; bu[2 * p + 1][1] = t[3];
            }
#pragma unroll
            for (int mt = 0; mt < 4; mt++)
#pragma unroll
                for (int nt = 0; nt < 4; nt++) {
                    mma16(accg[mt][nt], af[mt], bg[nt]);
                    mma16(accu[mt][nt], af[mt], bu[nt]);
                }
        }
    };

    const int nslab = Kd / BK;
    LDG(); STS(0);
    LDG(); STS(1);

    for (int t = 0; t < nslab / 2; t++) {
        __syncthreads();
        const int s0 = 2 * t, s1 = 2 * t + 1;
        const bool pf0 = (s0 + 2 < nslab), pf1 = (s1 + 2 < nslab);
        if (pf0) LDG();
        COMPUTE(s0 & 3);
        if (pf0) STS((s0 + 2) & 3);
        if (pf1) LDG();
        COMPUTE(s1 & 3);
        if (pf1) STS((s1 + 2) & 3);
    }

    // ---- epilogue: silu(g)*u, packed half2 stores ----
    __half* dstB = C + (EXPERT ? (size_t)e * sC : 0);
#pragma unroll
    for (int mt = 0; mt < 4; mt++)
#pragma unroll
        for (int nt = 0; nt < 4; nt++)
#pragma unroll
            for (int rp = 0; rp < 2; rp++) {      // r pairs (2rp, 2rp+1) -> adjacent cols
                int row = wm * 64 + mt * 16 + gq + rp * 8;
                int col = wn * 32 + nt * 8 + tq * 2;
                int gm = m0 + row;
                if (EXPERT && gm >= cnt) continue;
                float v0 = silu_f(accg[mt][nt][2 * rp])     * accu[mt][nt][2 * rp];
                float v1 = silu_f(accg[mt][nt][2 * rp + 1]) * accu[mt][nt][2 * rp + 1];
                *(uint32_t*)(dstB + (size_t)gm * ldc + n0 + col) = pack2(v0, v1);
            }
}

// ================= down GEMM (A in __half; BK=32, 8-slot ring, sync per 4 slabs) =================
template<int BNK, int EXPERT, int ATOMIC>
__global__ __launch_bounds__(NTH) void k_gemm(
    const __half* __restrict__ Abase, const float* __restrict__ Bbase,
    float* __restrict__ C, int Kd, int ldb, int ldc,
    long sA, long sB)
{
    extern __shared__ __align__(16) unsigned char smraw[];
    __shared__ int   s_tok[128];
    __shared__ float s_w[128];

    const int tid = threadIdx.x;
    const int warp = tid >> 5, lane = tid & 31;
    const int wm = warp >> 2, wn = warp & 3;
    const int gq = lane >> 2, tq = lane & 3;
    const int m0 = blockIdx.y * 128, n0 = blockIdx.x * 128;

    int e = 0, cnt = 0x40000000;
    if (EXPERT) {
        e = blockIdx.z;
        cnt = g_counts[e];
        if (m0 >= cnt) return;
    }
    if (ATOMIC) {
        if (tid < 128) {
            int p = m0 + tid;
            int ok = (p < cnt);
            s_tok[tid] = ok ? g_buf_tok[e * CAP + p] : 0;
            s_w[tid]   = ok ? g_buf_w[e * CAP + p] : 0.0f;
        }
        __syncthreads();
    }

    const uint32_t smb = smem_u32(smraw);

    // A loader: half source, 2 x 16B chunks per thread per slab (128 rows x 64B)
    const __half* pa[2];
    uint32_t stA[2];
#pragma unroll
    for (int j = 0; j < 2; j++) {
        int idx = tid + j * NTH;            // 0..511
        int m = idx >> 2, c = idx & 3;      // row, 16B chunk (8 halfs)
        pa[j] = Abase + (EXPERT ? (size_t)e * sA : 0) + (size_t)(m0 + m) * Kd + c * 8;
        stA[j] = (uint32_t)(m * RSA + c * 16);
    }
    const float* pb[4];
    uint32_t stB[4];
#pragma unroll
    for (int j = 0; j < 4; j++) {
        int idx = tid + j * NTH;
        if (BNK) {
            int n = idx >> 3, k8 = idx & 7;
            pb[j] = Bbase + (EXPERT ? (size_t)e * sB : 0) + (size_t)(n0 + n) * Kd + k8 * 4;
            stB[j] = (uint32_t)(n * RSA + k8 * 8);
        } else {
            int k = idx >> 5, n8 = idx & 31;
            pb[j] = Bbase + (EXPERT ? (size_t)e * sB : 0) + (size_t)k * ldb + n0 + n8 * 4;
            stB[j] = (uint32_t)(k * RSB + n8 * 8);
        }
    }
    const long bumpB = BNK ? (long)BK : (long)BK * ldb;

    uint4 ua[2];
    float4 rb[4];
    auto LDG = [&]() {
#pragma unroll
        for (int j = 0; j < 2; j++) { ua[j] = *(const uint4*)pa[j]; pa[j] += BK; }
#pragma unroll
        for (int j = 0; j < 4; j++) { rb[j] = *(const float4*)pb[j]; pb[j] += bumpB; }
    };
    auto STS = [&](int slot) {
        uint32_t aT = smb + slot * TSLOT;
        uint32_t bT = smb + 8 * TSLOT + slot * TSLOT;
#pragma unroll
        for (int j = 0; j < 2; j++) {
            asm volatile("st.shared.v4.u32 [%0], {%1, %2, %3, %4};"
                         :: "r"(aT + stA[j]), "r"(ua[j].x), "r"(ua[j].y), "r"(ua[j].z), "r"(ua[j].w));
        }
#pragma unroll
        for (int j = 0; j < 4; j++) {
            uint2 v = make_uint2(pack2(rb[j].x, rb[j].y), pack2(rb[j].z, rb[j].w));
            asm volatile("st.shared.v2.u32 [%0], {%1, %2};" :: "r"(bT + stB[j]), "r"(v.x), "r"(v.y));
        }
    };

    uint32_t aOff[4];
#pragma unroll
    for (int mt = 0; mt < 4; mt++) aOff[mt] = (uint32_t)((wm * 64 + mt * 16) * RSA) + LM_A(lane);
    uint32_t bOff[2];
#pragma unroll
    for (int p = 0; p < 2; p++)
        bOff[p] = BNK ? (uint32_t)((wn * 32 + p * 16) * RSA) + LM_BN(lane)
                      : (uint32_t)((wn * 32 + p * 16) * 2) + LM_BT(lane);

    float acc[4][4][4];
#pragma unroll
    for (int mt = 0; mt < 4; mt++)
#pragma unroll
        for (int nt = 0; nt < 4; nt++)
#pragma unroll
            for (int r = 0; r < 4; r++) acc[mt][nt][r] = 0.0f;

    auto COMPUTE = [&](int slot) {
        uint32_t aT = smb + slot * TSLOT;
        uint32_t bT = smb + 8 * TSLOT + slot * TSLOT;
#pragma unroll
        for (int kh = 0; kh < 2; kh++) {
            const uint32_t kA = kh * 32;
            const uint32_t kB = BNK ? (uint32_t)(kh * 32) : (uint32_t)(kh * 16 * RSB);
            uint32_t af[4][4];
#pragma unroll
            for (int mt = 0; mt < 4; mt++) ldsm4(af[mt], aT + aOff[mt] + kA);
            uint32_t bf[4][2];
#pragma unroll
            for (int p = 0; p < 2; p++) {
                uint32_t t[4];
                if (BNK) ldsm4(t, bT + bOff[p] + kB); else ldsm4t(t, bT + bOff[p] + kB);
                bf[2 * p][0] = t[0]; bf[2 * p][1] = t[1];
                bf[2 * p + 1][0] = t[2]; bf[2 * p + 1][1] = t[3];
            }
#pragma unroll
            for (int mt = 0; mt < 4; mt++)
#pragma unroll
                for (int nt = 0; nt < 4; nt++)
                    mma16(acc[mt][nt], af[mt], bf[nt]);
        }
    };

    const int nslab = Kd / BK;          // 48 or 24: divisible by 4
    LDG(); STS(0);
    LDG(); STS(1);
    LDG(); STS(2);
    LDG(); STS(3);

    for (int t = 0; t < nslab / 4; t++) {
        __syncthreads();
#pragma unroll
        for (int i = 0; i < 4; i++) {
            const int s = 4 * t + i;
            const bool pf = (s + 4 < nslab);
            if (pf) LDG();
            COMPUTE(s & 7);
            if (pf) STS((s + 4) & 7);
        }
    }

#pragma unroll
    for (int mt = 0; mt < 4; mt++)
#pragma unroll
        for (int nt = 0; nt < 4; nt++)
#pragma unroll
            for (int r = 0; r < 4; r++) {
                int row = wm * 64 + mt * 16 + gq + ((r & 2) ? 8 : 0);
                int col = wn * 32 + nt * 8 + tq * 2 + (r & 1);
                int gm = m0 + row;
                if (EXPERT && gm >= cnt) continue;
                if (ATOMIC) {
                    atomicAdd(&C[(size_t)s_tok[row] * ldc + n0 + col],
                              acc[mt][nt][r] * s_w[row]);
                } else {
                    C[(size_t)gm * ldc + n0 + col] = acc[mt][nt][r];
                }
            }
}

// ================= router logits: 3xTF32, K-split x4 (near-fp32, exact top-k) =================
#define RTH 128
__global__ __launch_bounds__(RTH) void k_router_gemm(const float* __restrict__ A,
                                                     const float* __restrict__ B) {
    __shared__ float As[16][64 + 4];
    __shared__ float Bsm[16][64 + 4];
    int tid = threadIdx.x;
    int warp = tid >> 5, lane = tid & 31;
    int wm = warp >> 1, wn = warp & 1, gq = lane >> 2, tq = lane & 3;
    int m0 = blockIdx.y * 64;
    int kc = blockIdx.x;
    int kbase = kc * RKLEN;

    const float* Ab = A + (size_t)m0 * HDIM + kbase;
    const float* Bb = B + kbase;

    float acc[2][4][4];
#pragma unroll
    for (int mt = 0; mt < 2; mt++)
#pragma unroll
        for (int nt = 0; nt < 4; nt++)
#pragma unroll
            for (int r = 0; r < 4; r++) acc[mt][nt][r] = 0.0f;

    for (int k0 = 0; k0 < RKLEN; k0 += 16) {
        __syncthreads();
#pragma unroll
        for (int j = 0; j < 2; j++) {
            int it = tid + j * RTH;
            int r = it >> 2, c4 = it & 3;
            float4 va = *(const float4*)(Ab + (size_t)r * HDIM + k0 + c4 * 4);
            As[c4 * 4 + 0][r] = va.x; As[c4 * 4 + 1][r] = va.y;
            As[c4 * 4 + 2][r] = va.z; As[c4 * 4 + 3][r] = va.w;
            float4 vb = *(const float4*)(Bb + (size_t)r * HDIM + k0 + c4 * 4);
            Bsm[c4 * 4 + 0][r] = vb.x; Bsm[c4 * 4 + 1][r] = vb.y;
            Bsm[c4 * 4 + 2][r] = vb.z; Bsm[c4 * 4 + 3][r] = vb.w;
        }
        __syncthreads();
#pragma unroll
        for (int kk = 0; kk < 16; kk += 8) {
            float af[2][4], bfv[4][2];
#pragma unroll
            for (int mt = 0; mt < 2; mt++) {
                int rb = wm * 32 + mt * 16;
                af[mt][0] = As[kk + tq    ][rb + gq    ];
                af[mt][1] = As[kk + tq    ][rb + gq + 8];
                af[mt][2] = As[kk + tq + 4][rb + gq    ];
                af[mt][3] = As[kk + tq + 4][rb + gq + 8];
            }
#pragma unroll
            for (int nt = 0; nt < 4; nt++) {
                int cb = wn * 32 + nt * 8 + gq;
                bfv[nt][0] = Bsm[kk + tq    ][cb];
                bfv[nt][1] = Bsm[kk + tq + 4][cb];
            }
            unsigned ah[2][4], al[2][4], bh[4][2], bl[4][2];
#pragma unroll
            for (int mt = 0; mt < 2; mt++)
#pragma unroll
                for (int i = 0; i < 4; i++) {
                    ah[mt][i] = f2tf(af[mt][i]);
                    al[mt][i] = f2tf(af[mt][i] - __uint_as_float(ah[mt][i]));
                }
#pragma unroll
            for (int nt = 0; nt < 4; nt++)
#pragma unroll
                for (int i = 0; i < 2; i++) {
                    bh[nt][i] = f2tf(bfv[nt][i]);
                    bl[nt][i] = f2tf(bfv[nt][i] - __uint_as_float(bh[nt][i]));
                }
#pragma unroll
            for (int mt = 0; mt < 2; mt++)
#pragma unroll
                for (int nt = 0; nt < 4; nt++) {
                    mma8(acc[mt][nt], al[mt], bh[nt]);
                    mma8(acc[mt][nt], ah[mt], bl[nt]);
                    mma8(acc[mt][nt], ah[mt], bh[nt]);
                }
        }
    }
    float* dst = g_logits_p + (size_t)kc * NTOK * NEXP;
#pragma unroll
    for (int mt = 0; mt < 2; mt++)
#pragma unroll
        for (int nt = 0; nt < 4; nt++)
#pragma unroll
            for (int r = 0; r < 4; r++) {
                int row = wm * 32 + mt * 16 + gq + ((r & 2) ? 8 : 0);
                int col = wn * 32 + nt * 8 + tq * 2 + (r & 1);
                dst[(size_t)(m0 + row) * NEXP + col] = acc[mt][nt][r];
            }
}

// ================= router softmax + top-6 + dispatch =================
__global__ void k_init() {
    if (threadIdx.x < NEXP) g_counts[threadIdx.x] = 0;
}

__global__ void k_router() {
    int warp = threadIdx.x >> 5, lane = threadIdx.x & 31;
    int t = blockIdx.x * 8 + warp;
    float v0 = 0.0f, v1 = 0.0f;
#pragma unroll
    for (int c = 0; c < RKC; c++) {
        v0 += g_logits_p[(size_t)c * NTOK * NEXP + t * NEXP + lane];
        v1 += g_logits_p[(size_t)c * NTOK * NEXP + t * NEXP + 32 + lane];
    }
    float m = fmaxf(v0, v1);
#pragma unroll
    for (int s = 16; s > 0; s >>= 1) m = fmaxf(m, __shfl_xor_sync(0xffffffffu, m, s));
    float e0 = expf(v0 - m), e1 = expf(v1 - m);
    float sum = e0 + e1;
#pragma unroll
    for (int s = 16; s > 0; s >>= 1) sum += __shfl_xor_sync(0xffffffffu, sum, s);
    float inv = 1.0f / sum;
    float p0 = e0 * inv, p1 = e1 * inv;

#pragma unroll
    for (int k = 0; k < TOPK; k++) {
        float bv; int bi;
        if (p0 >= p1) { bv = p0; bi = lane; } else { bv = p1; bi = lane + 32; }
#pragma unroll
        for (int s = 16; s > 0; s >>= 1) {
            float ov = __shfl_xor_sync(0xffffffffu, bv, s);
            int   oi = __shfl_xor_sync(0xffffffffu, bi, s);
            if (ov > bv || (ov == bv && oi < bi)) { bv = ov; bi = oi; }
        }
        if (lane == 0) {
            int pos = atomicAdd(&g_counts[bi], 1);
            if (pos < CAP) {
                g_buf_tok[bi * CAP + pos] = t;
                g_buf_w[bi * CAP + pos] = bv;
            }
        }
        if (bi < 32) { if (lane == bi) p0 = -1.0f; }
        else         { if (lane == bi - 32) p1 = -1.0f; }
    }
}

// ================= launch =================
extern "C" void kernel_launch(void* const* d_in, const int* in_sizes, int n_in,
                              void* d_out, int out_size) {
    const float* x   = (const float*)d_in[0];
    const float* gw  = (const float*)d_in[1];
    const float* gup = (const float*)d_in[2];
    const float* dwn = (const float*)d_in[3];
    const float* sgw = (const float*)d_in[4];
    const float* suw = (const float*)d_in[5];
    const float* sdw = (const float*)d_in[6];
    float* out = (float*)d_out;

    __half *p_hid, *p_shid;
    cudaGetSymbolAddress((void**)&p_hid,  g_hid);
    cudaGetSymbolAddress((void**)&p_shid, g_shid);

    cudaFuncSetAttribute(k_swiglu<1,0,0>, cudaFuncAttributeMaxDynamicSharedMemorySize, SWIGLU_SMEM);
    cudaFuncSetAttribute(k_swiglu<0,1,1>, cudaFuncAttributeMaxDynamicSharedMemorySize, SWIGLU_SMEM);
    cudaFuncSetAttribute(k_gemm<1,0,0>,   cudaFuncAttributeMaxDynamicSharedMemorySize, GEMM_SMEM);
    cudaFuncSetAttribute(k_gemm<0,1,1>,   cudaFuncAttributeMaxDynamicSharedMemorySize, GEMM_SMEM);

    k_init<<<1, 64>>>();
    // router: near-fp32 logits (K-split x4, deterministic reduce in k_router)
    k_router_gemm<<<dim3(RKC, NTOK / 64), RTH>>>(x, gw);
    k_router<<<NTOK / 8, 256>>>();

    // shared experts: fused SwiGLU up ([N,K] weights) -> fp16 shid, then down -> out
    k_swiglu<1,0,0><<<dim3(SIDIM / 128, NTOK / 128), NTH, SWIGLU_SMEM>>>(
        x, sgw, suw, p_shid, HDIM, 0, SIDIM, 0, 0);
    k_gemm<1,0,0><<<dim3(HDIM / 128, NTOK / 128), NTH, GEMM_SMEM>>>(
        p_shid, sdw, out, SIDIM, 0, HDIM, 0, 0);

    // routed experts: gate_up (gathered A) -> fp16 hid, down (atomic scatter-add)
    k_swiglu<0,1,1><<<dim3(IDIM / 128, CAP / 128, NEXP), NTH, SWIGLU_SMEM>>>(
        x, gup, gup + IDIM, p_hid, HDIM, TWOI, IDIM, (long)HDIM * TWOI, (long)CAP * IDIM);
    k_gemm<0,1,1><<<dim3(HDIM / 128, CAP / 128, NEXP), NTH, GEMM_SMEM>>>(
        p_hid, dwn, out, IDIM, HDIM, HDIM, (long)CAP * IDIM, (long)IDIM * HDIM);
}

// round 17
// speedup vs baseline: 1.3666x; 1.0783x over previous
#include <cuda_runtime.h>
#include <cuda_fp16.h>
#include <math.h>
#include <stdint.h>

// ---------------- problem constants ----------------
#define NTOK   2048
#define NEXP   64
#define TOPK   6
#define CAP    512
#define HDIM   2048
#define IDIM   768
#define TWOI   1536
#define SIDIM  1536

// ---------------- tile config ----------------
#define BK   32              // k per slab (halfs)
#define NTH  256             // 8 warps
#define RSA  80              // [row][k] tile row stride BYTES
#define RSB  272             // [k][n] tile row stride BYTES
#define TSLOT 10240          // bytes per tile slot
#define SWIGLU_SMEM (12 * TSLOT)  // 4-slot ring x (A,G,U) = 122880 B
#define GEMM_SMEM   (16 * TSLOT)  // 8-slot ring x (A,B)   = 163840 B

// merged grids
#define UP_SH_BLKS   (12 * 16)            // 192 shared swiglu tiles
#define UP_RT_PER_E  (6 * 4)              // 24 routed tiles per expert
#define UP_TOTAL     (UP_SH_BLKS + UP_RT_PER_E * NEXP)       // 1728
#define DN_SH_BLKS   (16 * 16)            // 256 shared down tiles
#define DN_RT_PER_E  (16 * 4)             // 64 routed tiles per expert
#define DN_TOTAL     (DN_SH_BLKS + DN_RT_PER_E * NEXP)       // 4352

// router K-split
#define RKC 4
#define RKLEN (HDIM / RKC)

// ---------------- scratch ----------------
__device__ int   g_counts[NEXP];
__device__ int   g_buf_tok[NEXP * CAP];
__device__ float g_buf_w[NEXP * CAP];
__device__ float g_logits_p[RKC * NTOK * NEXP];
__device__ float g_hid[(size_t)NEXP * CAP * IDIM];
__device__ float g_shid[(size_t)NTOK * SIDIM];

// ---------------- helpers ----------------
__device__ __forceinline__ uint32_t smem_u32(const void* p) {
    uint32_t a;
    asm("{ .reg .u64 t; cvta.to.shared.u64 t, %1; cvt.u32.u64 %0, t; }" : "=r"(a) : "l"(p));
    return a;
}
__device__ __forceinline__ uint32_t pack2(float a, float b) {
    __half2 h = __floats2half2_rn(a, b);
    return *(uint32_t*)&h;
}
__device__ __forceinline__ void ldsm4(uint32_t r[4], uint32_t addr) {
    asm volatile("ldmatrix.sync.aligned.m8n8.x4.shared.b16 {%0,%1,%2,%3}, [%4];"
                 : "=r"(r[0]), "=r"(r[1]), "=r"(r[2]), "=r"(r[3]) : "r"(addr));
}
__device__ __forceinline__ void ldsm4t(uint32_t r[4], uint32_t addr) {
    asm volatile("ldmatrix.sync.aligned.m8n8.x4.trans.shared.b16 {%0,%1,%2,%3}, [%4];"
                 : "=r"(r[0]), "=r"(r[1]), "=r"(r[2]), "=r"(r[3]) : "r"(addr));
}
__device__ __forceinline__ void mma16(float c[4], const uint32_t a[4], const uint32_t b[2]) {
    asm volatile(
        "mma.sync.aligned.m16n8k16.row.col.f32.f16.f16.f32 "
        "{%0,%1,%2,%3}, {%4,%5,%6,%7}, {%8,%9}, {%0,%1,%2,%3};"
        : "+f"(c[0]), "+f"(c[1]), "+f"(c[2]), "+f"(c[3])
        : "r"(a[0]), "r"(a[1]), "r"(a[2]), "r"(a[3]), "r"(b[0]), "r"(b[1]));
}
__device__ __forceinline__ unsigned f2tf(float x) {
    unsigned y;
    asm("cvt.rna.tf32.f32 %0, %1;" : "=r"(y) : "f"(x));
    return y;
}
__device__ __forceinline__ void mma8(float c[4], const unsigned a[4], const unsigned b[2]) {
    asm volatile(
        "mma.sync.aligned.m16n8k8.row.col.f32.tf32.tf32.f32 "
        "{%0,%1,%2,%3}, {%4,%5,%6,%7}, {%8,%9}, {%0,%1,%2,%3};"
        : "+f"(c[0]), "+f"(c[1]), "+f"(c[2]), "+f"(c[3])
        : "r"(a[0]), "r"(a[1]), "r"(a[2]), "r"(a[3]), "r"(b[0]), "r"(b[1]));
}
__device__ __forceinline__ float silu_f(float v) { return v / (1.0f + expf(-v)); }

#define LM_A(lane)  (((((lane) >> 3) & 1) * 8 + ((lane) & 7)) * RSA + ((lane) >> 4) * 16)
#define LM_BN(lane) ((((lane) >> 4) * 8 + ((lane) & 7)) * RSA + (((lane) >> 3) & 1) * 16)
#define LM_BT(lane) (((((lane) >> 3) & 1) * 8 + ((lane) & 7)) * RSB + ((lane) >> 4) * 16)

// ================= SwiGLU body (fp16 engine, BK=32, 4-slot ring) =================
template<int BNK, int EXPERT, int GATHER>
__device__ void swiglu_body(
    const float* __restrict__ Abase, const float* __restrict__ Bg0,
    const float* __restrict__ Bu0, float* __restrict__ C,
    int Kd, int ldb, int ldc, long sB, long sC,
    int bx, int by, int eidx)
{
    extern __shared__ __align__(16) unsigned char smraw[];
    __shared__ int s_tok[128];

    const int tid = threadIdx.x;
    const int warp = tid >> 5, lane = tid & 31;
    const int wm = warp >> 2, wn = warp & 3;
    const int gq = lane >> 2, tq = lane & 3;
    const int m0 = by * 128, n0 = bx * 128;

    int e = 0, cnt = 0x40000000;
    if (EXPERT) {
        e = eidx;
        cnt = g_counts[e];
        if (m0 >= cnt) return;
    }
    if (GATHER) {
        if (tid < 128) {
            int p = m0 + tid;
            s_tok[tid] = (p < cnt) ? g_buf_tok[e * CAP + p] : 0;
        }
        __syncthreads();
    }

    const uint32_t smb = smem_u32(smraw);

    const float* pa[4];
    uint32_t stA[4];
#pragma unroll
    for (int j = 0; j < 4; j++) {
        int idx = tid + j * NTH;
        int m = idx >> 3, k8 = idx & 7;
        if (GATHER) pa[j] = Abase + (size_t)s_tok[m] * Kd + k8 * 4;
        else        pa[j] = Abase + (size_t)(m0 + m) * Kd + k8 * 4;
        stA[j] = (uint32_t)(m * RSA + k8 * 8);
    }
    const float* pg[4]; const float* pu[4];
    uint32_t stB[4];
#pragma unroll
    for (int j = 0; j < 4; j++) {
        int idx = tid + j * NTH;
        if (BNK) {
            int n = idx >> 3, k8 = idx & 7;
            pg[j] = Bg0 + (EXPERT ? (size_t)e * sB : 0) + (size_t)(n0 + n) * Kd + k8 * 4;
            pu[j] = Bu0 + (EXPERT ? (size_t)e * sB : 0) + (size_t)(n0 + n) * Kd + k8 * 4;
            stB[j] = (uint32_t)(n * RSA + k8 * 8);
        } else {
            int k = idx >> 5, n8 = idx & 31;
            pg[j] = Bg0 + (EXPERT ? (size_t)e * sB : 0) + (size_t)k * ldb + n0 + n8 * 4;
            pu[j] = Bu0 + (EXPERT ? (size_t)e * sB : 0) + (size_t)k * ldb + n0 + n8 * 4;
            stB[j] = (uint32_t)(k * RSB + n8 * 8);
        }
    }
    const long bumpB = BNK ? (long)BK : (long)BK * ldb;

    float4 ra[4], rg[4], ru[4];
    auto LDG = [&]() {
#pragma unroll
        for (int j = 0; j < 4; j++) { ra[j] = *(const float4*)pa[j]; pa[j] += BK; }
#pragma unroll
        for (int j = 0; j < 4; j++) { rg[j] = *(const float4*)pg[j]; pg[j] += bumpB; }
#pragma unroll
        for (int j = 0; j < 4; j++) { ru[j] = *(const float4*)pu[j]; pu[j] += bumpB; }
    };
    auto STS = [&](int slot) {
        uint32_t aT = smb + slot * TSLOT;
        uint32_t gT = smb + 4 * TSLOT + slot * TSLOT;
        uint32_t uT = smb + 8 * TSLOT + slot * TSLOT;
#pragma unroll
        for (int j = 0; j < 4; j++) {
            uint2 v = make_uint2(pack2(ra[j].x, ra[j].y), pack2(ra[j].z, ra[j].w));
            asm volatile("st.shared.v2.u32 [%0], {%1, %2};" :: "r"(aT + stA[j]), "r"(v.x), "r"(v.y));
        }
#pragma unroll
        for (int j = 0; j < 4; j++) {
            uint2 vg = make_uint2(pack2(rg[j].x, rg[j].y), pack2(rg[j].z, rg[j].w));
            asm volatile("st.shared.v2.u32 [%0], {%1, %2};" :: "r"(gT + stB[j]), "r"(vg.x), "r"(vg.y));
            uint2 vu = make_uint2(pack2(ru[j].x, ru[j].y), pack2(ru[j].z, ru[j].w));
            asm volatile("st.shared.v2.u32 [%0], {%1, %2};" :: "r"(uT + stB[j]), "r"(vu.x), "r"(vu.y));
        }
    };

    uint32_t aOff[4];
#pragma unroll
    for (int mt = 0; mt < 4; mt++) aOff[mt] = (uint32_t)((wm * 64 + mt * 16) * RSA) + LM_A(lane);
    uint32_t bOff[2];
#pragma unroll
    for (int p = 0; p < 2; p++)
        bOff[p] = BNK ? (uint32_t)((wn * 32 + p * 16) * RSA) + LM_BN(lane)
                      : (uint32_t)((wn * 32 + p * 16) * 2) + LM_BT(lane);

    float accg[4][4][4], accu[4][4][4];
#pragma unroll
    for (int mt = 0; mt < 4; mt++)
#pragma unroll
        for (int nt = 0; nt < 4; nt++)
#pragma unroll
            for (int r = 0; r < 4; r++) { accg[mt][nt][r] = 0.0f; accu[mt][nt][r] = 0.0f; }

    auto COMPUTE = [&](int slot) {
        uint32_t aT = smb + slot * TSLOT;
        uint32_t gT = smb + 4 * TSLOT + slot * TSLOT;
        uint32_t uT = smb + 8 * TSLOT + slot * TSLOT;
#pragma unroll
        for (int kh = 0; kh < 2; kh++) {
            const uint32_t kA = kh * 32;
            const uint32_t kB = BNK ? (uint32_t)(kh * 32) : (uint32_t)(kh * 16 * RSB);
            uint32_t af[4][4];
#pragma unroll
            for (int mt = 0; mt < 4; mt++) ldsm4(af[mt], aT + aOff[mt] + kA);
            uint32_t bg[4][2], bu[4][2];
#pragma unroll
            for (int p = 0; p < 2; p++) {
                uint32_t t[4];
                if (BNK) ldsm4(t, gT + bOff[p] + kB); else ldsm4t(t, gT + bOff[p] + kB);
                bg[2 * p][0] = t[0]; bg[2 * p][1] = t[1];
                bg[2 * p + 1][0] = t[2]; bg[2 * p + 1][1] = t[3];
                if (BNK) ldsm4(t, uT + bOff[p] + kB); else ldsm4t(t, uT + bOff[p] + kB);
                bu[2 * p][0] = t[0]; bu[2 * p][1] = t[1];
                bu[2 * p + 1][0] = t[2]; bu[2 * p + 1][1] = t[3];
            }
#pragma unroll
            for (int mt = 0; mt < 4; mt++)
#pragma unroll
                for (int nt = 0; nt < 4; nt++) {
                    mma16(accg[mt][nt], af[mt], bg[nt]);
                    mma16(accu[mt][nt], af[mt], bu[nt]);
                }
        }
    };

    const int nslab = Kd / BK;
    LDG(); STS(0);
    LDG(); STS(1);

    for (int t = 0; t < nslab / 2; t++) {
        __syncthreads();
        const int s0 = 2 * t, s1 = 2 * t + 1;
        const bool pf0 = (s0 + 2 < nslab), pf1 = (s1 + 2 < nslab);
        if (pf0) LDG();
        COMPUTE(s0 & 3);
        if (pf0) STS((s0 + 2) & 3);
        if (pf1) LDG();
        COMPUTE(s1 & 3);
        if (pf1) STS((s1 + 2) & 3);
    }

    float* dst = C + (EXPERT ? (size_t)e * sC : 0);
#pragma unroll
    for (int mt = 0; mt < 4; mt++)
#pragma unroll
        for (int nt = 0; nt < 4; nt++)
#pragma unroll
            for (int r = 0; r < 4; r++) {
                int row = wm * 64 + mt * 16 + gq + ((r & 2) ? 8 : 0);
                int col = wn * 32 + nt * 8 + tq * 2 + (r & 1);
                int gm = m0 + row;
                if (EXPERT && gm >= cnt) continue;
                float g = accg[mt][nt][r], u = accu[mt][nt][r];
                dst[(size_t)gm * ldc + n0 + col] = silu_f(g) * u;
            }
}

// ================= down GEMM body (BK=32, 8-slot ring, sync per 4 slabs) =================
// MODE 1: routed — atomicAdd(out[tok]) * gate weight.  MODE 2: direct atomicAdd(out[row]).
template<int BNK, int EXPERT, int MODE>
__device__ void gemm_body(
    const float* __restrict__ Abase, const float* __restrict__ Bbase,
    float* __restrict__ C, int Kd, int ldb, int ldc,
    long sA, long sB, int bx, int by, int eidx)
{
    extern __shared__ __align__(16) unsigned char smraw[];
    __shared__ int   s_tok[128];
    __shared__ float s_w[128];

    const int tid = threadIdx.x;
    const int warp = tid >> 5, lane = tid & 31;
    const int wm = warp >> 2, wn = warp & 3;
    const int gq = lane >> 2, tq = lane & 3;
    const int m0 = by * 128, n0 = bx * 128;

    int e = 0, cnt = 0x40000000;
    if (EXPERT) {
        e = eidx;
        cnt = g_counts[e];
        if (m0 >= cnt) return;
    }
    if (MODE == 1) {
        if (tid < 128) {
            int p = m0 + tid;
            int ok = (p < cnt);
            s_tok[tid] = ok ? g_buf_tok[e * CAP + p] : 0;
            s_w[tid]   = ok ? g_buf_w[e * CAP + p] : 0.0f;
        }
        __syncthreads();
    }

    const uint32_t smb = smem_u32(smraw);

    const float* pa[4];
    uint32_t stA[4];
#pragma unroll
    for (int j = 0; j < 4; j++) {
        int idx = tid + j * NTH;
        int m = idx >> 3, k8 = idx & 7;
        pa[j] = Abase + (EXPERT ? (size_t)e * sA : 0) + (size_t)(m0 + m) * Kd + k8 * 4;
        stA[j] = (uint32_t)(m * RSA + k8 * 8);
    }
    const float* pb[4];
    uint32_t stB[4];
#pragma unroll
    for (int j = 0; j < 4; j++) {
        int idx = tid + j * NTH;
        if (BNK) {
            int n = idx >> 3, k8 = idx & 7;
            pb[j] = Bbase + (EXPERT ? (size_t)e * sB : 0) + (size_t)(n0 + n) * Kd + k8 * 4;
            stB[j] = (uint32_t)(n * RSA + k8 * 8);
        } else {
            int k = idx >> 5, n8 = idx & 31;
            pb[j] = Bbase + (EXPERT ? (size_t)e * sB : 0) + (size_t)k * ldb + n0 + n8 * 4;
            stB[j] = (uint32_t)(k * RSB + n8 * 8);
        }
    }
    const long bumpB = BNK ? (long)BK : (long)BK * ldb;

    float4 ra[4], rb[4];
    auto LDG = [&]() {
#pragma unroll
        for (int j = 0; j < 4; j++) { ra[j] = *(const float4*)pa[j]; pa[j] += BK; }
#pragma unroll
        for (int j = 0; j < 4; j++) { rb[j] = *(const float4*)pb[j]; pb[j] += bumpB; }
    };
    auto STS = [&](int slot) {
        uint32_t aT = smb + slot * TSLOT;
        uint32_t bT = smb + 8 * TSLOT + slot * TSLOT;
#pragma unroll
        for (int j = 0; j < 4; j++) {
            uint2 v = make_uint2(pack2(ra[j].x, ra[j].y), pack2(ra[j].z, ra[j].w));
            asm volatile("st.shared.v2.u32 [%0], {%1, %2};" :: "r"(aT + stA[j]), "r"(v.x), "r"(v.y));
        }
#pragma unroll
        for (int j = 0; j < 4; j++) {
            uint2 v = make_uint2(pack2(rb[j].x, rb[j].y), pack2(rb[j].z, rb[j].w));
            asm volatile("st.shared.v2.u32 [%0], {%1, %2};" :: "r"(bT + stB[j]), "r"(v.x), "r"(v.y));
        }
    };

    uint32_t aOff[4];
#pragma unroll
    for (int mt = 0; mt < 4; mt++) aOff[mt] = (uint32_t)((wm * 64 + mt * 16) * RSA) + LM_A(lane);
    uint32_t bOff[2];
#pragma unroll
    for (int p = 0; p < 2; p++)
        bOff[p] = BNK ? (uint32_t)((wn * 32 + p * 16) * RSA) + LM_BN(lane)
                      : (uint32_t)((wn * 32 + p * 16) * 2) + LM_BT(lane);

    float acc[4][4][4];
#pragma unroll
    for (int mt = 0; mt < 4; mt++)
#pragma unroll
        for (int nt = 0; nt < 4; nt++)
#pragma unroll
            for (int r = 0; r < 4; r++) acc[mt][nt][r] = 0.0f;

    auto COMPUTE = [&](int slot) {
        uint32_t aT = smb + slot * TSLOT;
        uint32_t bT = smb + 8 * TSLOT + slot * TSLOT;
#pragma unroll
        for (int kh = 0; kh < 2; kh++) {
            const uint32_t kA = kh * 32;
            const uint32_t kB = BNK ? (uint32_t)(kh * 32) : (uint32_t)(kh * 16 * RSB);
            uint32_t af[4][4];
#pragma unroll
            for (int mt = 0; mt < 4; mt++) ldsm4(af[mt], aT + aOff[mt] + kA);
            uint32_t bf[4][2];
#pragma unroll
            for (int p = 0; p < 2; p++) {
                uint32_t t[4];
                if (BNK) ldsm4(t, bT + bOff[p] + kB); else ldsm4t(t, bT + bOff[p] + kB);
                bf[2 * p][0] = t[0]; bf[2 * p][1] = t[1];
                bf[2 * p + 1][0] = t[2]; bf[2 * p + 1][1] = t[3];
            }
#pragma unroll
            for (int mt = 0; mt < 4; mt++)
#pragma unroll
                for (int nt = 0; nt < 4; nt++)
                    mma16(acc[mt][nt], af[mt], bf[nt]);
        }
    };

    const int nslab = Kd / BK;          // 48 or 24
    LDG(); STS(0);
    LDG(); STS(1);
    LDG(); STS(2);
    LDG(); STS(3);

    for (int t = 0; t < nslab / 4; t++) {
        __syncthreads();
#pragma unroll
        for (int i = 0; i < 4; i++) {
            const int s = 4 * t + i;
            const bool pf = (s + 4 < nslab);
            if (pf) LDG();
            COMPUTE(s & 7);
            if (pf) STS((s + 4) & 7);
        }
    }

#pragma unroll
    for (int mt = 0; mt < 4; mt++)
#pragma unroll
        for (int nt = 0; nt < 4; nt++)
#pragma unroll
            for (int r = 0; r < 4; r++) {
                int row = wm * 64 + mt * 16 + gq + ((r & 2) ? 8 : 0);
                int col = wn * 32 + nt * 8 + tq * 2 + (r & 1);
                int gm = m0 + row;
                if (EXPERT && gm >= cnt) continue;
                if (MODE == 1) {
                    atomicAdd(&C[(size_t)s_tok[row] * ldc + n0 + col],
                              acc[mt][nt][r] * s_w[row]);
                } else {
                    atomicAdd(&C[(size_t)gm * ldc + n0 + col], acc[mt][nt][r]);
                }
            }
}

// ================= merged launches =================
// up: shared swiglu tiles first (full blocks), then routed expert tiles (early-exit past cnt)
__global__ __launch_bounds__(NTH) void k_up_all(
    const float* __restrict__ x, const float* __restrict__ sgw,
    const float* __restrict__ suw, float* __restrict__ shid,
    const float* __restrict__ gup, float* __restrict__ hid)
{
    int b = blockIdx.x;
    if (b < UP_SH_BLKS) {
        swiglu_body<1, 0, 0>(x, sgw, suw, shid, HDIM, 0, SIDIM, 0, 0,
                             b % 12, b / 12, 0);
    } else {
        int r = b - UP_SH_BLKS;
        int e = r / UP_RT_PER_E, rr = r % UP_RT_PER_E;
        swiglu_body<0, 1, 1>(x, gup, gup + IDIM, hid, HDIM, TWOI, IDIM,
                             (long)HDIM * TWOI, (long)CAP * IDIM,
                             rr % 6, rr / 6, e);
    }
}

// down: shared down tiles (direct atomic into zeroed out), then routed (tok-scatter atomic)
__global__ __launch_bounds__(NTH) void k_down_all(
    const float* __restrict__ shid, const float* __restrict__ sdw,
    const float* __restrict__ hid, const float* __restrict__ dwn,
    float* __restrict__ out)
{
    int b = blockIdx.x;
    if (b < DN_SH_BLKS) {
        gemm_body<1, 0, 2>(shid, sdw, out, SIDIM, 0, HDIM, 0, 0,
                           b % 16, b / 16, 0);
    } else {
        int r = b - DN_SH_BLKS;
        int e = r / DN_RT_PER_E, rr = r % DN_RT_PER_E;
        gemm_body<0, 1, 1>(hid, dwn, out, IDIM, HDIM, HDIM,
                           (long)CAP * IDIM, (long)IDIM * HDIM,
                           rr % 16, rr / 16, e);
    }
}

// ================= router logits: 3xTF32, K-split x4 (near-fp32, exact top-k) =================
#define RTH 128
__global__ __launch_bounds__(RTH) void k_router_gemm(const float* __restrict__ A,
                                                     const float* __restrict__ B) {
    __shared__ float As[16][64 + 4];
    __shared__ float Bsm[16][64 + 4];
    int tid = threadIdx.x;
    int warp = tid >> 5, lane = tid & 31;
    int wm = warp >> 1, wn = warp & 1, gq = lane >> 2, tq = lane & 3;
    int m0 = blockIdx.y * 64;
    int kc = blockIdx.x;
    int kbase = kc * RKLEN;

    const float* Ab = A + (size_t)m0 * HDIM + kbase;
    const float* Bb = B + kbase;

    float acc[2][4][4];
#pragma unroll
    for (int mt = 0; mt < 2; mt++)
#pragma unroll
        for (int nt = 0; nt < 4; nt++)
#pragma unroll
            for (int r = 0; r < 4; r++) acc[mt][nt][r] = 0.0f;

    for (int k0 = 0; k0 < RKLEN; k0 += 16) {
        __syncthreads();
#pragma unroll
        for (int j = 0; j < 2; j++) {
            int it = tid + j * RTH;
            int r = it >> 2, c4 = it & 3;
            float4 va = *(const float4*)(Ab + (size_t)r * HDIM + k0 + c4 * 4);
            As[c4 * 4 + 0][r] = va.x; As[c4 * 4 + 1][r] = va.y;
            As[c4 * 4 + 2][r] = va.z; As[c4 * 4 + 3][r] = va.w;
            float4 vb = *(const float4*)(Bb + (size_t)r * HDIM + k0 + c4 * 4);
            Bsm[c4 * 4 + 0][r] = vb.x; Bsm[c4 * 4 + 1][r] = vb.y;
            Bsm[c4 * 4 + 2][r] = vb.z; Bsm[c4 * 4 + 3][r] = vb.w;
        }
        __syncthreads();
#pragma unroll
        for (int kk = 0; kk < 16; kk += 8) {
            float af[2][4], bfv[4][2];
#pragma unroll
            for (int mt = 0; mt < 2; mt++) {
                int rb = wm * 32 + mt * 16;
                af[mt][0] = As[kk + tq    ][rb + gq    ];
                af[mt][1] = As[kk + tq    ][rb + gq + 8];
                af[mt][2] = As[kk + tq + 4][rb + gq    ];
                af[mt][3] = As[kk + tq + 4][rb + gq + 8];
            }
#pragma unroll
            for (int nt = 0; nt < 4; nt++) {
                int cb = wn * 32 + nt * 8 + gq;
                bfv[nt][0] = Bsm[kk + tq    ][cb];
                bfv[nt][1] = Bsm[kk + tq + 4][cb];
            }
            unsigned ah[2][4], al[2][4], bh[4][2], bl[4][2];
#pragma unroll
            for (int mt = 0; mt < 2; mt++)
#pragma unroll
                for (int i = 0; i < 4; i++) {
                    ah[mt][i] = f2tf(af[mt][i]);
                    al[mt][i] = f2tf(af[mt][i] - __uint_as_float(ah[mt][i]));
                }
#pragma unroll
            for (int nt = 0; nt < 4; nt++)
#pragma unroll
                for (int i = 0; i < 2; i++) {
                    bh[nt][i] = f2tf(bfv[nt][i]);
                    bl[nt][i] = f2tf(bfv[nt][i] - __uint_as_float(bh[nt][i]));
                }
#pragma unroll
            for (int mt = 0; mt < 2; mt++)
#pragma unroll
                for (int nt = 0; nt < 4; nt++) {
                    mma8(acc[mt][nt], al[mt], bh[nt]);
                    mma8(acc[mt][nt], ah[mt], bl[nt]);
                    mma8(acc[mt][nt], ah[mt], bh[nt]);
                }
        }
    }
    float* dst = g_logits_p + (size_t)kc * NTOK * NEXP;
#pragma unroll
    for (int mt = 0; mt < 2; mt++)
#pragma unroll
        for (int nt = 0; nt < 4; nt++)
#pragma unroll
            for (int r = 0; r < 4; r++) {
                int row = wm * 32 + mt * 16 + gq + ((r & 2) ? 8 : 0);
                int col = wn * 32 + nt * 8 + tq * 2 + (r & 1);
                dst[(size_t)(m0 + row) * NEXP + col] = acc[mt][nt][r];
            }
}

// ================= router softmax + top-6 + dispatch =================
__global__ void k_init() {
    if (threadIdx.x < NEXP) g_counts[threadIdx.x] = 0;
}

__global__ void k_router() {
    int warp = threadIdx.x >> 5, lane = threadIdx.x & 31;
    int t = blockIdx.x * 8 + warp;
    float v0 = 0.0f, v1 = 0.0f;
#pragma unroll
    for (int c = 0; c < RKC; c++) {
        v0 += g_logits_p[(size_t)c * NTOK * NEXP + t * NEXP + lane];
        v1 += g_logits_p[(size_t)c * NTOK * NEXP + t * NEXP + 32 + lane];
    }
    float m = fmaxf(v0, v1);
#pragma unroll
    for (int s = 16; s > 0; s >>= 1) m = fmaxf(m, __shfl_xor_sync(0xffffffffu, m, s));
    float e0 = expf(v0 - m), e1 = expf(v1 - m);
    float sum = e0 + e1;
#pragma unroll
    for (int s = 16; s > 0; s >>= 1) sum += __shfl_xor_sync(0xffffffffu, sum, s);
    float inv = 1.0f / sum;
    float p0 = e0 * inv, p1 = e1 * inv;

#pragma unroll
    for (int k = 0; k < TOPK; k++) {
        float bv; int bi;
        if (p0 >= p1) { bv = p0; bi = lane; } else { bv = p1; bi = lane + 32; }
#pragma unroll
        for (int s = 16; s > 0; s >>= 1) {
            float ov = __shfl_xor_sync(0xffffffffu, bv, s);
            int   oi = __shfl_xor_sync(0xffffffffu, bi, s);
            if (ov > bv || (ov == bv && oi < bi)) { bv = ov; bi = oi; }
        }
        if (lane == 0) {
            int pos = atomicAdd(&g_counts[bi], 1);
            if (pos < CAP) {
                g_buf_tok[bi * CAP + pos] = t;
                g_buf_w[bi * CAP + pos] = bv;
            }
        }
        if (bi < 32) { if (lane == bi) p0 = -1.0f; }
        else         { if (lane == bi - 32) p1 = -1.0f; }
    }
}

// ================= launch =================
extern "C" void kernel_launch(void* const* d_in, const int* in_sizes, int n_in,
                              void* d_out, int out_size) {
    const float* x   = (const float*)d_in[0];
    const float* gw  = (const float*)d_in[1];
    const float* gup = (const float*)d_in[2];
    const float* dwn = (const float*)d_in[3];
    const float* sgw = (const float*)d_in[4];
    const float* suw = (const float*)d_in[5];
    const float* sdw = (const float*)d_in[6];
    float* out = (float*)d_out;

    float *p_hid, *p_shid;
    cudaGetSymbolAddress((void**)&p_hid,  g_hid);
    cudaGetSymbolAddress((void**)&p_shid, g_shid);

    cudaFuncSetAttribute(k_up_all,   cudaFuncAttributeMaxDynamicSharedMemorySize, SWIGLU_SMEM);
    cudaFuncSetAttribute(k_down_all, cudaFuncAttributeMaxDynamicSharedMemorySize, GEMM_SMEM);

    k_init<<<1, 64>>>();
    cudaMemsetAsync(out, 0, (size_t)out_size * sizeof(float));
    // router: near-fp32 logits (K-split x4, deterministic reduce in k_router)
    k_router_gemm<<<dim3(RKC, NTOK / 64), RTH>>>(x, gw);
    k_router<<<NTOK / 8, 256>>>();

    // merged up-projections (shared tiles + routed expert tiles, single packed launch)
    k_up_all<<<UP_TOTAL, NTH, SWIGLU_SMEM>>>(x, sgw, suw, p_shid, gup, p_hid);
    // merged down-projections (shared direct-atomic + routed scatter-atomic)
    k_down_all<<<DN_TOTAL, NTH, GEMM_SMEM>>>(p_shid, sdw, p_hid, dwn, out);
}